// round 1
// baseline (speedup 1.0000x reference)
#include <cuda_runtime.h>
#include <math.h>

#define SEQ 2048
#define H 16
#define KVH 8
#define D 128
#define HID 2048
#define INTERM 8192

// ---------------- scratch (device globals; no allocation allowed) ----------------
__device__ float g_xn[SEQ * HID];
__device__ float g_q[SEQ * H * D];
__device__ float g_k[SEQ * KVH * D];
__device__ float g_v[SEQ * KVH * D];
__device__ float g_sc[(size_t)H * SEQ * SEQ];   // 256 MB scores/probs
__device__ float g_ao[SEQ * H * D];
__device__ float g_h[SEQ * HID];
__device__ float g_y[SEQ * HID];
__device__ float g_gate[SEQ * INTERM];
__device__ float g_up[SEQ * INTERM];

// ---------------- RMSNorm: one block per row ----------------
__global__ void rmsnorm_kernel(const float* __restrict__ x, const float* __restrict__ w,
                               float* __restrict__ out, int dim) {
    int row = blockIdx.x;
    const float* xr = x + (size_t)row * dim;
    float ss = 0.f;
    for (int i = threadIdx.x; i < dim; i += blockDim.x) { float v = xr[i]; ss += v * v; }
    __shared__ float red[32];
    for (int o = 16; o; o >>= 1) ss += __shfl_xor_sync(~0u, ss, o);
    if ((threadIdx.x & 31) == 0) red[threadIdx.x >> 5] = ss;
    __syncthreads();
    if (threadIdx.x < 32) {
        float v = (threadIdx.x < (blockDim.x >> 5)) ? red[threadIdx.x] : 0.f;
        for (int o = 16; o; o >>= 1) v += __shfl_xor_sync(~0u, v, o);
        if (threadIdx.x == 0) red[0] = v;
    }
    __syncthreads();
    float inv = rsqrtf(red[0] / (float)dim + 1e-6f);
    for (int i = threadIdx.x; i < dim; i += blockDim.x)
        out[(size_t)row * dim + i] = xr[i] * inv * w[i];
}

// ---------------- SGEMM NT: C[M,N] = alpha*(A[M,K] @ B[N,K]^T) + add ----------------
// 64x64 block tile, BK=16, 256 threads, 4x4 per thread micro-tile.
__global__ void __launch_bounds__(256) sgemm_nt(
    const float* __restrict__ A, int lda,
    const float* __restrict__ B, int ldb,
    float* __restrict__ C, int ldc,
    const float* __restrict__ add, float alpha, int K) {
    __shared__ float As[16][64];
    __shared__ float Bs[16][64];
    int tid = threadIdx.x;
    int tx = tid & 15, ty = tid >> 4;
    int m0 = blockIdx.y * 64, n0 = blockIdx.x * 64;
    float acc[4][4] = {};
    int lr = tid >> 2;          // 0..63
    int lk = (tid & 3) * 4;     // 0,4,8,12
    const float* Ap = A + (size_t)(m0 + lr) * lda + lk;
    const float* Bp = B + (size_t)(n0 + lr) * ldb + lk;
    for (int kt = 0; kt < K; kt += 16) {
        float4 a = *(const float4*)(Ap + kt);
        float4 b = *(const float4*)(Bp + kt);
        As[lk + 0][lr] = a.x; As[lk + 1][lr] = a.y; As[lk + 2][lr] = a.z; As[lk + 3][lr] = a.w;
        Bs[lk + 0][lr] = b.x; Bs[lk + 1][lr] = b.y; Bs[lk + 2][lr] = b.z; Bs[lk + 3][lr] = b.w;
        __syncthreads();
#pragma unroll
        for (int kk = 0; kk < 16; kk++) {
            float4 av = *(const float4*)&As[kk][ty * 4];
            float4 bv = *(const float4*)&Bs[kk][tx * 4];
            float ar[4] = {av.x, av.y, av.z, av.w};
            float br[4] = {bv.x, bv.y, bv.z, bv.w};
#pragma unroll
            for (int i = 0; i < 4; i++)
#pragma unroll
                for (int j = 0; j < 4; j++) acc[i][j] += ar[i] * br[j];
        }
        __syncthreads();
    }
#pragma unroll
    for (int i = 0; i < 4; i++) {
        int r = m0 + ty * 4 + i;
        size_t off = (size_t)r * ldc + n0 + tx * 4;
        float4 c;
        c.x = alpha * acc[i][0]; c.y = alpha * acc[i][1];
        c.z = alpha * acc[i][2]; c.w = alpha * acc[i][3];
        if (add) {
            float4 d = *(const float4*)(add + off);
            c.x += d.x; c.y += d.y; c.z += d.z; c.w += d.w;
        }
        *(float4*)(C + off) = c;
    }
}

// ---------------- SGEMM NN: C[M,N] = A[M,K] @ B[K,N] ----------------
__global__ void __launch_bounds__(256) sgemm_nn(
    const float* __restrict__ A, int lda,
    const float* __restrict__ B, int ldb,
    float* __restrict__ C, int ldc, int K) {
    __shared__ float As[16][64];
    __shared__ float Bs[16][64];
    int tid = threadIdx.x;
    int tx = tid & 15, ty = tid >> 4;
    int m0 = blockIdx.y * 64, n0 = blockIdx.x * 64;
    float acc[4][4] = {};
    int lr = tid >> 2;
    int lk = (tid & 3) * 4;
    int bk = tid >> 4;          // 0..15
    int bc = (tid & 15) * 4;    // 0..60
    const float* Ap = A + (size_t)(m0 + lr) * lda + lk;
    const float* Bp = B + (size_t)bk * ldb + n0 + bc;
    for (int kt = 0; kt < K; kt += 16) {
        float4 a = *(const float4*)(Ap + kt);
        float4 b = *(const float4*)(Bp + (size_t)kt * ldb);
        As[lk + 0][lr] = a.x; As[lk + 1][lr] = a.y; As[lk + 2][lr] = a.z; As[lk + 3][lr] = a.w;
        *(float4*)&Bs[bk][bc] = b;
        __syncthreads();
#pragma unroll
        for (int kk = 0; kk < 16; kk++) {
            float4 av = *(const float4*)&As[kk][ty * 4];
            float4 bv = *(const float4*)&Bs[kk][tx * 4];
            float ar[4] = {av.x, av.y, av.z, av.w};
            float br[4] = {bv.x, bv.y, bv.z, bv.w};
#pragma unroll
            for (int i = 0; i < 4; i++)
#pragma unroll
                for (int j = 0; j < 4; j++) acc[i][j] += ar[i] * br[j];
        }
        __syncthreads();
    }
#pragma unroll
    for (int i = 0; i < 4; i++) {
        int r = m0 + ty * 4 + i;
        size_t off = (size_t)r * ldc + n0 + tx * 4;
        *(float4*)(C + off) = make_float4(acc[i][0], acc[i][1], acc[i][2], acc[i][3]);
    }
}

// ---------------- RoPE on q and k in place ----------------
__global__ void rope_kernel(float* __restrict__ q, float* __restrict__ k,
                            const int* __restrict__ pos) {
    int idx = blockIdx.x * blockDim.x + threadIdx.x;
    const int total = SEQ * (H + KVH) * 64;
    if (idx >= total) return;
    int j = idx & 63;                       // rotary pair index 0..63
    int slot = (idx >> 6) % (H + KVH);
    int srow = idx / (64 * (H + KVH));
    float p = (float)pos[srow];
    float invf = __expf(-(float)j * (logf(10000.f) / 64.f));
    float ang = p * invf;
    float c = cosf(ang), sn = sinf(ang);
    float* base;
    if (slot < H) base = q + (size_t)srow * (H * D) + slot * D;
    else          base = k + (size_t)srow * (KVH * D) + (slot - H) * D;
    float x0 = base[j], x1 = base[j + 64];
    base[j]      = x0 * c - x1 * sn;
    base[j + 64] = x1 * c + x0 * sn;
}

// ---------------- masked softmax over scores rows (mask = same-sid & causal) ----------------
__global__ void softmax_kernel(float* __restrict__ sc, const int* __restrict__ sid) {
    int i = blockIdx.x;
    int h = blockIdx.y;
    float* row = sc + ((size_t)h * SEQ + i) * SEQ;
    __shared__ float sh[SEQ];
    __shared__ float red[32];
    int tid = threadIdx.x;
    int sidi = sid[i];
    float mx = -1e30f;
    for (int j = tid; j < SEQ; j += blockDim.x) {
        float v = row[j];
        bool ok = (j <= i) && (sid[j] == sidi);
        v = ok ? v : -1e30f;
        sh[j] = v;
        mx = fmaxf(mx, v);
    }
    for (int o = 16; o; o >>= 1) mx = fmaxf(mx, __shfl_xor_sync(~0u, mx, o));
    if ((tid & 31) == 0) red[tid >> 5] = mx;
    __syncthreads();
    if (tid < 32) {
        float v = (tid < (blockDim.x >> 5)) ? red[tid] : -1e30f;
        for (int o = 16; o; o >>= 1) v = fmaxf(v, __shfl_xor_sync(~0u, v, o));
        if (tid == 0) red[0] = v;
    }
    __syncthreads();
    float m = red[0];
    float sum = 0.f;
    for (int j = tid; j < SEQ; j += blockDim.x) {
        float v = sh[j];
        float e = (v > -1e29f) ? expf(v - m) : 0.f;
        sh[j] = e;
        sum += e;
    }
    __syncthreads();   // everyone has read red[0] before we overwrite red
    for (int o = 16; o; o >>= 1) sum += __shfl_xor_sync(~0u, sum, o);
    if ((tid & 31) == 0) red[tid >> 5] = sum;
    __syncthreads();
    if (tid < 32) {
        float v = (tid < (blockDim.x >> 5)) ? red[tid] : 0.f;
        for (int o = 16; o; o >>= 1) v += __shfl_xor_sync(~0u, v, o);
        if (tid == 0) red[0] = v;
    }
    __syncthreads();
    float inv = 1.f / red[0];
    for (int j = tid; j < SEQ; j += blockDim.x) row[j] = sh[j] * inv;
}

// ---------------- silu(gate) * up, in place into gate ----------------
__global__ void silu_mul_kernel(float* __restrict__ g, const float* __restrict__ u, size_t n) {
    size_t i = (size_t)blockIdx.x * blockDim.x + threadIdx.x;
    if (i < n) {
        float x = g[i];
        float s = 1.f / (1.f + expf(-x));
        g[i] = x * s * u[i];
    }
}

extern "C" void kernel_launch(void* const* d_in, const int* in_sizes, int n_in,
                              void* d_out, int out_size) {
    const float* hs  = (const float*)d_in[0];
    const int*   sid = (const int*)d_in[1];
    const int*   pos = (const int*)d_in[2];
    const float* ln1 = (const float*)d_in[3];
    const float* wq  = (const float*)d_in[4];
    const float* wk  = (const float*)d_in[5];
    const float* wv  = (const float*)d_in[6];
    const float* wo  = (const float*)d_in[7];
    const float* ln2 = (const float*)d_in[8];
    const float* wg  = (const float*)d_in[9];
    const float* wu  = (const float*)d_in[10];
    const float* wd  = (const float*)d_in[11];
    float* out = (float*)d_out;

    float *xn, *q, *k, *v, *sc, *ao, *hb, *y, *gb, *ub;
    cudaGetSymbolAddress((void**)&xn, g_xn);
    cudaGetSymbolAddress((void**)&q,  g_q);
    cudaGetSymbolAddress((void**)&k,  g_k);
    cudaGetSymbolAddress((void**)&v,  g_v);
    cudaGetSymbolAddress((void**)&sc, g_sc);
    cudaGetSymbolAddress((void**)&ao, g_ao);
    cudaGetSymbolAddress((void**)&hb, g_h);
    cudaGetSymbolAddress((void**)&y,  g_y);
    cudaGetSymbolAddress((void**)&gb, g_gate);
    cudaGetSymbolAddress((void**)&ub, g_up);

    const float scale = 0.08838834764831845f;  // 1/sqrt(128)

    // 1. pre-attention RMSNorm
    rmsnorm_kernel<<<SEQ, 256>>>(hs, ln1, xn, HID);

    // 2. QKV projections
    sgemm_nt<<<dim3((H * D) / 64, SEQ / 64), 256>>>(xn, HID, wq, HID, q, H * D, nullptr, 1.f, HID);
    sgemm_nt<<<dim3((KVH * D) / 64, SEQ / 64), 256>>>(xn, HID, wk, HID, k, KVH * D, nullptr, 1.f, HID);
    sgemm_nt<<<dim3((KVH * D) / 64, SEQ / 64), 256>>>(xn, HID, wv, HID, v, KVH * D, nullptr, 1.f, HID);

    // 3. RoPE
    rope_kernel<<<(SEQ * (H + KVH) * 64 + 255) / 256, 256>>>(q, k, pos);

    // 4. scores = scale * Q @ K^T per head (GQA: kv head = h/2)
    for (int h = 0; h < H; h++) {
        sgemm_nt<<<dim3(SEQ / 64, SEQ / 64), 256>>>(
            q + h * D, H * D, k + (h >> 1) * D, KVH * D,
            sc + (size_t)h * SEQ * SEQ, SEQ, nullptr, scale, D);
    }

    // 5. masked softmax (mask = same-sid & causal; window is inactive at s=2048)
    softmax_kernel<<<dim3(SEQ, H), 256>>>(sc, sid);

    // 6. O = P @ V per head
    for (int h = 0; h < H; h++) {
        sgemm_nn<<<dim3(D / 64, SEQ / 64), 256>>>(
            sc + (size_t)h * SEQ * SEQ, SEQ, v + (h >> 1) * D, KVH * D,
            ao + h * D, H * D, SEQ);
    }

    // 7. h = resid + attn_out @ Wo^T
    sgemm_nt<<<dim3(HID / 64, SEQ / 64), 256>>>(ao, H * D, wo, H * D, hb, HID, hs, 1.f, H * D);

    // 8. post-attention RMSNorm
    rmsnorm_kernel<<<SEQ, 256>>>(hb, ln2, y, HID);

    // 9. MLP: gate, up, silu*mul, down + residual (written straight to d_out)
    sgemm_nt<<<dim3(INTERM / 64, SEQ / 64), 256>>>(y, HID, wg, HID, gb, INTERM, nullptr, 1.f, HID);
    sgemm_nt<<<dim3(INTERM / 64, SEQ / 64), 256>>>(y, HID, wu, HID, ub, INTERM, nullptr, 1.f, HID);
    silu_mul_kernel<<<(SEQ * INTERM + 255) / 256, 256>>>(gb, ub, (size_t)SEQ * INTERM);
    sgemm_nt<<<dim3(HID / 64, SEQ / 64), 256>>>(gb, INTERM, wd, INTERM, out, HID, hb, 1.f, INTERM);
}

// round 3
// speedup vs baseline: 2.3247x; 2.3247x over previous
#include <cuda_runtime.h>
#include <cuda_bf16.h>
#include <cstdint>
#include <math.h>

#define SEQ 2048
#define H 16
#define KVH 8
#define D 128
#define HID 2048
#define INTERM 8192

// ---------------- scratch (device globals) ----------------
__device__ float g_xn[SEQ * HID];
__device__ float g_q[SEQ * H * D];
__device__ float g_k[SEQ * KVH * D];
__device__ float g_v[SEQ * KVH * D];
__device__ float g_vt[KVH * D * SEQ];           // V transposed: [kvh*D][SEQ]
__device__ float g_sc[(size_t)H * SEQ * SEQ];   // 256 MB scores/probs
__device__ float g_ao[SEQ * H * D];
__device__ float g_h[SEQ * HID];
__device__ float g_y[SEQ * HID];
__device__ float g_gate[SEQ * INTERM];
__device__ float g_up[SEQ * INTERM];

// ================= helpers =================
__device__ __forceinline__ uint32_t smem_to_u32(const void* p) {
    uint32_t a;
    asm("{ .reg .u64 t; cvta.to.shared.u64 t, %1; cvt.u32.u64 %0, t; }" : "=r"(a) : "l"(p));
    return a;
}
__device__ __forceinline__ uint32_t pack_bf16(float lo, float hi) {
    uint32_t r;
    asm("cvt.rn.satfinite.bf16x2.f32 %0, %1, %2;" : "=r"(r) : "f"(hi), "f"(lo));
    return r;
}
__device__ __forceinline__ void ldsm4(uint32_t* r, uint32_t addr) {
    asm volatile("ldmatrix.sync.aligned.m8n8.x4.shared.b16 {%0,%1,%2,%3}, [%4];"
                 : "=r"(r[0]), "=r"(r[1]), "=r"(r[2]), "=r"(r[3]) : "r"(addr));
}
__device__ __forceinline__ void mma16816(float* c, const uint32_t* a, const uint32_t* b) {
    asm volatile(
        "mma.sync.aligned.m16n8k16.row.col.f32.bf16.bf16.f32 "
        "{%0,%1,%2,%3}, {%4,%5,%6,%7}, {%8,%9}, {%0,%1,%2,%3};"
        : "+f"(c[0]), "+f"(c[1]), "+f"(c[2]), "+f"(c[3])
        : "r"(a[0]), "r"(a[1]), "r"(a[2]), "r"(a[3]), "r"(b[0]), "r"(b[1]));
}

// smem layout per stage (40960 B): A_hi[128][40]bf16 @0, A_lo @10240, B_hi @20480, B_lo @30720
#define STAGE_BYTES 40960
#define HM_SMEM (2 * STAGE_BYTES)

// C[M,N] = alpha * A[M,K] @ B[N,K]^T (+ add). fp32 in/out, split-bf16 HMMA core.
// Block tile 128x128, K chunk 32, 256 threads (8 warps: 4 M x 2 N, warp tile 32x64).
__global__ void __launch_bounds__(256) hmma_gemm(
    const float* __restrict__ A, int lda, long long sA,
    const float* __restrict__ B, int ldb, long long sB, int bshift,
    float* __restrict__ C, int ldc, long long sC,
    const float* __restrict__ add, float alpha, int K) {
    extern __shared__ char sm[];
    const int tid = threadIdx.x;
    const int lane = tid & 31, wid = tid >> 5;
    const int wm = wid >> 1, wn = wid & 1;
    const int z = blockIdx.z;
    A += (size_t)z * sA;
    B += (size_t)(z >> bshift) * sB;
    C += (size_t)z * sC;
    const int m0 = blockIdx.y * 128, n0 = blockIdx.x * 128;

    const uint32_t sb = smem_to_u32(sm);
    const int lrow = lane & 15;
    const uint32_t lcol = (uint32_t)(lane >> 4) * 16;
    const uint32_t aoff = sb + (uint32_t)(wm * 32 + lrow) * 80 + lcol;          // A_hi
    const uint32_t boff = sb + 20480 + (uint32_t)(wn * 64 + lrow) * 80 + lcol;  // B_hi

    // global loader: thread t -> row t>>1, 16 cols starting at (t&1)*16
    const int grow = tid >> 1;
    const int gcol = (tid & 1) * 16;
    const float* Ap = A + (size_t)(m0 + grow) * lda + gcol;
    const float* Bp = B + (size_t)(n0 + grow) * ldb + gcol;
    const uint32_t stA = (uint32_t)grow * 80 + (uint32_t)gcol * 2;
    const uint32_t stB = 20480 + stA;

    float acc[2][8][4];
#pragma unroll
    for (int i = 0; i < 2; i++)
#pragma unroll
        for (int j = 0; j < 8; j++)
#pragma unroll
            for (int l = 0; l < 4; l++) acc[i][j][l] = 0.f;

    const int nk = K >> 5;
    float4 la[4], lbv[4];

#define LOADG(kt) do { \
    const float* _ap = Ap + (kt) * 32; \
    const float* _bp = Bp + (kt) * 32; \
    _Pragma("unroll") \
    for (int i = 0; i < 4; i++) { la[i] = *(const float4*)(_ap + i * 4); lbv[i] = *(const float4*)(_bp + i * 4); } \
} while (0)

#define STORES(st) do { \
    char* _s = sm + (st) * STAGE_BYTES; \
    _Pragma("unroll") \
    for (int i = 0; i < 4; i++) { \
        uint32_t h01 = pack_bf16(la[i].x, la[i].y), h23 = pack_bf16(la[i].z, la[i].w); \
        float f0 = __uint_as_float(h01 << 16), f1 = __uint_as_float(h01 & 0xffff0000u); \
        float f2 = __uint_as_float(h23 << 16), f3 = __uint_as_float(h23 & 0xffff0000u); \
        uint32_t l01 = pack_bf16(la[i].x - f0, la[i].y - f1), l23 = pack_bf16(la[i].z - f2, la[i].w - f3); \
        *(uint2*)(_s + stA + i * 8) = make_uint2(h01, h23); \
        *(uint2*)(_s + 10240 + stA + i * 8) = make_uint2(l01, l23); \
        h01 = pack_bf16(lbv[i].x, lbv[i].y); h23 = pack_bf16(lbv[i].z, lbv[i].w); \
        f0 = __uint_as_float(h01 << 16); f1 = __uint_as_float(h01 & 0xffff0000u); \
        f2 = __uint_as_float(h23 << 16); f3 = __uint_as_float(h23 & 0xffff0000u); \
        l01 = pack_bf16(lbv[i].x - f0, lbv[i].y - f1); l23 = pack_bf16(lbv[i].z - f2, lbv[i].w - f3); \
        *(uint2*)(_s + stB + i * 8) = make_uint2(h01, h23); \
        *(uint2*)(_s + 10240 + stB + i * 8) = make_uint2(l01, l23); \
    } \
} while (0)

    // prologue
    LOADG(0);
    STORES(0);
    __syncthreads();

    for (int kt = 0; kt < nk; kt++) {
        const uint32_t so = (uint32_t)(kt & 1) * STAGE_BYTES;
        const bool more = (kt + 1) < nk;
        if (more) LOADG(kt + 1);

#pragma unroll
        for (int kk = 0; kk < 2; kk++) {
            uint32_t ah[2][4], al[2][4];
#pragma unroll
            for (int mt = 0; mt < 2; mt++) {
                ldsm4(ah[mt], aoff + so + mt * 1280 + kk * 32);
                ldsm4(al[mt], aoff + so + 10240 + mt * 1280 + kk * 32);
            }
            {
                uint32_t bh[4][4];
#pragma unroll
                for (int g = 0; g < 4; g++) ldsm4(bh[g], boff + so + g * 1280 + kk * 32);
#pragma unroll
                for (int mt = 0; mt < 2; mt++)
#pragma unroll
                    for (int nt = 0; nt < 8; nt++) {
                        const int g = nt >> 1, o = nt & 1;
                        uint32_t bf[2] = {bh[g][o], bh[g][o + 2]};
                        mma16816(acc[mt][nt], ah[mt], bf);
                        mma16816(acc[mt][nt], al[mt], bf);
                    }
            }
            {
                uint32_t bl[4][4];
#pragma unroll
                for (int g = 0; g < 4; g++) ldsm4(bl[g], boff + so + 10240 + g * 1280 + kk * 32);
#pragma unroll
                for (int mt = 0; mt < 2; mt++)
#pragma unroll
                    for (int nt = 0; nt < 8; nt++) {
                        const int g = nt >> 1, o = nt & 1;
                        uint32_t bf[2] = {bl[g][o], bl[g][o + 2]};
                        mma16816(acc[mt][nt], ah[mt], bf);
                    }
            }
        }
        if (more) STORES((kt + 1) & 1);
        __syncthreads();
    }

    // epilogue
    const int rb = m0 + wm * 32 + (lane >> 2);
    const int cb = n0 + wn * 64 + (lane & 3) * 2;
#pragma unroll
    for (int mt = 0; mt < 2; mt++)
#pragma unroll
        for (int nt = 0; nt < 8; nt++) {
            const int r0 = rb + mt * 16;
            const int c = cb + nt * 8;
            float2 v0 = make_float2(alpha * acc[mt][nt][0], alpha * acc[mt][nt][1]);
            float2 v1 = make_float2(alpha * acc[mt][nt][2], alpha * acc[mt][nt][3]);
            if (add) {
                float2 d0 = *(const float2*)(add + (size_t)r0 * ldc + c);
                float2 d1 = *(const float2*)(add + (size_t)(r0 + 8) * ldc + c);
                v0.x += d0.x; v0.y += d0.y; v1.x += d1.x; v1.y += d1.y;
            }
            *(float2*)(C + (size_t)r0 * ldc + c) = v0;
            *(float2*)(C + (size_t)(r0 + 8) * ldc + c) = v1;
        }
}

// ================= fp32 support kernels =================
__global__ void rmsnorm_kernel(const float* __restrict__ x, const float* __restrict__ w,
                               float* __restrict__ out, int dim) {
    int row = blockIdx.x;
    const float* xr = x + (size_t)row * dim;
    float ss = 0.f;
    for (int i = threadIdx.x; i < dim; i += blockDim.x) { float v = xr[i]; ss += v * v; }
    __shared__ float red[32];
    for (int o = 16; o; o >>= 1) ss += __shfl_xor_sync(~0u, ss, o);
    if ((threadIdx.x & 31) == 0) red[threadIdx.x >> 5] = ss;
    __syncthreads();
    if (threadIdx.x < 32) {
        float v = (threadIdx.x < (blockDim.x >> 5)) ? red[threadIdx.x] : 0.f;
        for (int o = 16; o; o >>= 1) v += __shfl_xor_sync(~0u, v, o);
        if (threadIdx.x == 0) red[0] = v;
    }
    __syncthreads();
    float inv = rsqrtf(red[0] / (float)dim + 1e-6f);
    for (int i = threadIdx.x; i < dim; i += blockDim.x)
        out[(size_t)row * dim + i] = xr[i] * inv * w[i];
}

__global__ void rope_kernel(float* __restrict__ q, float* __restrict__ k,
                            const int* __restrict__ pos) {
    int idx = blockIdx.x * blockDim.x + threadIdx.x;
    const int total = SEQ * (H + KVH) * 64;
    if (idx >= total) return;
    int j = idx & 63;
    int slot = (idx >> 6) % (H + KVH);
    int srow = idx / (64 * (H + KVH));
    float p = (float)pos[srow];
    float invf = __expf(-(float)j * (logf(10000.f) / 64.f));
    float ang = p * invf;
    float c = cosf(ang), sn = sinf(ang);
    float* base;
    if (slot < H) base = q + (size_t)srow * (H * D) + slot * D;
    else          base = k + (size_t)srow * (KVH * D) + (slot - H) * D;
    float x0 = base[j], x1 = base[j + 64];
    base[j]      = x0 * c - x1 * sn;
    base[j + 64] = x1 * c + x0 * sn;
}

__global__ void transpose_v(const float* __restrict__ v, float* __restrict__ vt) {
    __shared__ float t[32][33];
    int s0 = blockIdx.x * 32, c0 = blockIdx.y * 32;
    int tx = threadIdx.x, ty = threadIdx.y;
#pragma unroll
    for (int i = 0; i < 4; i++)
        t[ty + 8 * i][tx] = v[(size_t)(s0 + ty + 8 * i) * (KVH * D) + c0 + tx];
    __syncthreads();
#pragma unroll
    for (int i = 0; i < 4; i++)
        vt[(size_t)(c0 + ty + 8 * i) * SEQ + s0 + tx] = t[tx][ty + 8 * i];
}

__global__ void softmax_kernel(float* __restrict__ sc, const int* __restrict__ sid) {
    int i = blockIdx.x;
    int h = blockIdx.y;
    float* row = sc + ((size_t)h * SEQ + i) * SEQ;
    __shared__ float sh[SEQ];
    __shared__ float red[32];
    int tid = threadIdx.x;
    int sidi = sid[i];
    float mx = -1e30f;
    for (int j = tid; j < SEQ; j += blockDim.x) {
        float v = row[j];
        bool ok = (j <= i) && (sid[j] == sidi);
        v = ok ? v : -1e30f;
        sh[j] = v;
        mx = fmaxf(mx, v);
    }
    for (int o = 16; o; o >>= 1) mx = fmaxf(mx, __shfl_xor_sync(~0u, mx, o));
    if ((tid & 31) == 0) red[tid >> 5] = mx;
    __syncthreads();
    if (tid < 32) {
        float v = (tid < (blockDim.x >> 5)) ? red[tid] : -1e30f;
        for (int o = 16; o; o >>= 1) v = fmaxf(v, __shfl_xor_sync(~0u, v, o));
        if (tid == 0) red[0] = v;
    }
    __syncthreads();
    float m = red[0];
    float sum = 0.f;
    for (int j = tid; j < SEQ; j += blockDim.x) {
        float v = sh[j];
        float e = (v > -1e29f) ? __expf(v - m) : 0.f;
        sh[j] = e;
        sum += e;
    }
    __syncthreads();
    for (int o = 16; o; o >>= 1) sum += __shfl_xor_sync(~0u, sum, o);
    if ((tid & 31) == 0) red[tid >> 5] = sum;
    __syncthreads();
    if (tid < 32) {
        float v = (tid < (blockDim.x >> 5)) ? red[tid] : 0.f;
        for (int o = 16; o; o >>= 1) v += __shfl_xor_sync(~0u, v, o);
        if (tid == 0) red[0] = v;
    }
    __syncthreads();
    float inv = 1.f / red[0];
    for (int j = tid; j < SEQ; j += blockDim.x) row[j] = sh[j] * inv;
}

__global__ void silu_mul_kernel(float* __restrict__ g, const float* __restrict__ u, size_t n) {
    size_t i = (size_t)blockIdx.x * blockDim.x + threadIdx.x;
    if (i < n) {
        float x = g[i];
        float s = 1.f / (1.f + __expf(-x));
        g[i] = x * s * u[i];
    }
}

extern "C" void kernel_launch(void* const* d_in, const int* in_sizes, int n_in,
                              void* d_out, int out_size) {
    const float* hs  = (const float*)d_in[0];
    const int*   sid = (const int*)d_in[1];
    const int*   pos = (const int*)d_in[2];
    const float* ln1 = (const float*)d_in[3];
    const float* wq  = (const float*)d_in[4];
    const float* wk  = (const float*)d_in[5];
    const float* wv  = (const float*)d_in[6];
    const float* wo  = (const float*)d_in[7];
    const float* ln2 = (const float*)d_in[8];
    const float* wg  = (const float*)d_in[9];
    const float* wu  = (const float*)d_in[10];
    const float* wd  = (const float*)d_in[11];
    float* out = (float*)d_out;

    float *xn, *q, *k, *v, *vt, *sc, *ao, *hb, *y, *gb, *ub;
    cudaGetSymbolAddress((void**)&xn, g_xn);
    cudaGetSymbolAddress((void**)&q,  g_q);
    cudaGetSymbolAddress((void**)&k,  g_k);
    cudaGetSymbolAddress((void**)&v,  g_v);
    cudaGetSymbolAddress((void**)&vt, g_vt);
    cudaGetSymbolAddress((void**)&sc, g_sc);
    cudaGetSymbolAddress((void**)&ao, g_ao);
    cudaGetSymbolAddress((void**)&hb, g_h);
    cudaGetSymbolAddress((void**)&y,  g_y);
    cudaGetSymbolAddress((void**)&gb, g_gate);
    cudaGetSymbolAddress((void**)&ub, g_up);

    cudaFuncSetAttribute(hmma_gemm, cudaFuncAttributeMaxDynamicSharedMemorySize, HM_SMEM);

    const float scale = 0.08838834764831845f;  // 1/sqrt(128)

    // 1. pre-attention RMSNorm
    rmsnorm_kernel<<<SEQ, 256>>>(hs, ln1, xn, HID);

    // 2. QKV projections
    hmma_gemm<<<dim3(16, 16, 1), 256, HM_SMEM>>>(xn, HID, 0, wq, HID, 0, 0, q, H * D, 0, nullptr, 1.f, HID);
    hmma_gemm<<<dim3(8, 16, 1), 256, HM_SMEM>>>(xn, HID, 0, wk, HID, 0, 0, k, KVH * D, 0, nullptr, 1.f, HID);
    hmma_gemm<<<dim3(8, 16, 1), 256, HM_SMEM>>>(xn, HID, 0, wv, HID, 0, 0, v, KVH * D, 0, nullptr, 1.f, HID);

    // 3. RoPE + V transpose
    rope_kernel<<<(SEQ * (H + KVH) * 64 + 255) / 256, 256>>>(q, k, pos);
    transpose_v<<<dim3(SEQ / 32, (KVH * D) / 32), dim3(32, 8)>>>(v, vt);

    // 4. scores = scale * Q @ K^T, batched over 16 heads (kv head = z>>1)
    hmma_gemm<<<dim3(16, 16, H), 256, HM_SMEM>>>(
        q, H * D, D, k, KVH * D, D, 1,
        sc, SEQ, (long long)SEQ * SEQ, nullptr, scale, D);

    // 5. masked softmax (same-sid & causal; window inactive at s=2048)
    softmax_kernel<<<dim3(SEQ, H), 256>>>(sc, sid);

    // 6. O = P @ V (NT against transposed V), batched over heads
    hmma_gemm<<<dim3(1, 16, H), 256, HM_SMEM>>>(
        sc, SEQ, (long long)SEQ * SEQ, vt, SEQ, (long long)D * SEQ, 1,
        ao, H * D, D, nullptr, 1.f, SEQ);

    // 7. h = resid + attn_out @ Wo^T
    hmma_gemm<<<dim3(16, 16, 1), 256, HM_SMEM>>>(ao, H * D, 0, wo, H * D, 0, 0, hb, HID, 0, hs, 1.f, H * D);

    // 8. post-attention RMSNorm
    rmsnorm_kernel<<<SEQ, 256>>>(hb, ln2, y, HID);

    // 9. MLP
    hmma_gemm<<<dim3(64, 16, 1), 256, HM_SMEM>>>(y, HID, 0, wg, HID, 0, 0, gb, INTERM, 0, nullptr, 1.f, HID);
    hmma_gemm<<<dim3(64, 16, 1), 256, HM_SMEM>>>(y, HID, 0, wu, HID, 0, 0, ub, INTERM, 0, nullptr, 1.f, HID);
    silu_mul_kernel<<<(SEQ * INTERM + 255) / 256, 256>>>(gb, ub, (size_t)SEQ * INTERM);
    hmma_gemm<<<dim3(16, 16, 1), 256, HM_SMEM>>>(gb, INTERM, 0, wd, INTERM, 0, 0, out, HID, 0, hb, 1.f, INTERM);
}

// round 4
// speedup vs baseline: 2.9065x; 1.2503x over previous
#include <cuda_runtime.h>
#include <cuda_bf16.h>
#include <cstdint>
#include <math.h>

#define SEQ 2048
#define H 16
#define KVH 8
#define D 128
#define HID 2048
#define INTERM 8192
#define SCALE 0.08838834764831845f

// ---------------- scratch (device globals) ----------------
__device__ float g_xn[SEQ * HID];
__device__ float g_q[SEQ * H * D];
__device__ float g_k[SEQ * KVH * D];
__device__ float g_v[SEQ * KVH * D];
__device__ float g_ao[SEQ * H * D];
__device__ float g_h[SEQ * HID];
__device__ float g_y[SEQ * HID];
__device__ float g_gate[SEQ * INTERM];
__device__ float g_up[SEQ * INTERM];

// ================= helpers =================
__device__ __forceinline__ uint32_t smem_to_u32(const void* p) {
    uint32_t a;
    asm("{ .reg .u64 t; cvta.to.shared.u64 t, %1; cvt.u32.u64 %0, t; }" : "=r"(a) : "l"(p));
    return a;
}
__device__ __forceinline__ uint32_t pack_bf16(float lo, float hi) {
    uint32_t r;
    asm("cvt.rn.satfinite.bf16x2.f32 %0, %1, %2;" : "=r"(r) : "f"(hi), "f"(lo));
    return r;
}
__device__ __forceinline__ void ldsm4(uint32_t* r, uint32_t addr) {
    asm volatile("ldmatrix.sync.aligned.m8n8.x4.shared.b16 {%0,%1,%2,%3}, [%4];"
                 : "=r"(r[0]), "=r"(r[1]), "=r"(r[2]), "=r"(r[3]) : "r"(addr));
}
__device__ __forceinline__ void mma16816(float* c, const uint32_t* a, const uint32_t* b) {
    asm volatile(
        "mma.sync.aligned.m16n8k16.row.col.f32.bf16.bf16.f32 "
        "{%0,%1,%2,%3}, {%4,%5,%6,%7}, {%8,%9}, {%0,%1,%2,%3};"
        : "+f"(c[0]), "+f"(c[1]), "+f"(c[2]), "+f"(c[3])
        : "r"(a[0]), "r"(a[1]), "r"(a[2]), "r"(a[3]), "r"(b[0]), "r"(b[1]));
}
// split fp32x4 -> bf16 hi uint2 + lo uint2
__device__ __forceinline__ void split_store(char* dh, char* dl, float4 a) {
    uint32_t h01 = pack_bf16(a.x, a.y), h23 = pack_bf16(a.z, a.w);
    float f0 = __uint_as_float(h01 << 16), f1 = __uint_as_float(h01 & 0xffff0000u);
    float f2 = __uint_as_float(h23 << 16), f3 = __uint_as_float(h23 & 0xffff0000u);
    *(uint2*)dh = make_uint2(h01, h23);
    *(uint2*)dl = make_uint2(pack_bf16(a.x - f0, a.y - f1), pack_bf16(a.z - f2, a.w - f3));
}

// =================================================================
// hmma_gemm: C[M,N] = alpha * A[M,K] @ B[N,K]^T (+ add). split-bf16.
// 128x128 tile, K chunk 32, 256 threads (8 warps: 4Mx2N, warp 32x64).
// =================================================================
#define STAGE_BYTES 40960
#define HM_SMEM (2 * STAGE_BYTES)

__global__ void __launch_bounds__(256, 2) hmma_gemm(
    const float* __restrict__ A, int lda, long long sA,
    const float* __restrict__ B, int ldb, long long sB, int bshift,
    float* __restrict__ C, int ldc, long long sC,
    const float* __restrict__ add, float alpha, int K) {
    extern __shared__ char sm[];
    const int tid = threadIdx.x;
    const int lane = tid & 31, wid = tid >> 5;
    const int wm = wid >> 1, wn = wid & 1;
    const int z = blockIdx.z;
    A += (size_t)z * sA;
    B += (size_t)(z >> bshift) * sB;
    C += (size_t)z * sC;
    const int m0 = blockIdx.y * 128, n0 = blockIdx.x * 128;

    const uint32_t sb = smem_to_u32(sm);
    const int lrow = lane & 15;
    const uint32_t lcol = (uint32_t)(lane >> 4) * 16;
    const uint32_t aoff = sb + (uint32_t)(wm * 32 + lrow) * 80 + lcol;
    const uint32_t boff = sb + 20480 + (uint32_t)(wn * 64 + lrow) * 80 + lcol;

    const int grow = tid >> 1;
    const int gcol = (tid & 1) * 16;
    const float* Ap = A + (size_t)(m0 + grow) * lda + gcol;
    const float* Bp = B + (size_t)(n0 + grow) * ldb + gcol;
    const uint32_t stA = (uint32_t)grow * 80 + (uint32_t)gcol * 2;
    const uint32_t stB = 20480 + stA;

    float acc[2][8][4];
#pragma unroll
    for (int i = 0; i < 2; i++)
#pragma unroll
        for (int j = 0; j < 8; j++)
#pragma unroll
            for (int l = 0; l < 4; l++) acc[i][j][l] = 0.f;

    const int nk = K >> 5;
    float4 la[4], lbv[4];

#define LOADG(kt) do { \
    const float* _ap = Ap + (kt) * 32; \
    const float* _bp = Bp + (kt) * 32; \
    _Pragma("unroll") \
    for (int i = 0; i < 4; i++) { la[i] = *(const float4*)(_ap + i * 4); lbv[i] = *(const float4*)(_bp + i * 4); } \
} while (0)

#define STORES(st) do { \
    char* _s = sm + (st) * STAGE_BYTES; \
    _Pragma("unroll") \
    for (int i = 0; i < 4; i++) { \
        split_store(_s + stA + i * 8, _s + 10240 + stA + i * 8, la[i]); \
        split_store(_s + stB + i * 8, _s + 10240 + stB + i * 8, lbv[i]); \
    } \
} while (0)

    LOADG(0);
    STORES(0);
    __syncthreads();

    for (int kt = 0; kt < nk; kt++) {
        const uint32_t so = (uint32_t)(kt & 1) * STAGE_BYTES;
        const bool more = (kt + 1) < nk;
        if (more) LOADG(kt + 1);

#pragma unroll
        for (int kk = 0; kk < 2; kk++) {
            uint32_t ah[2][4], al[2][4];
#pragma unroll
            for (int mt = 0; mt < 2; mt++) {
                ldsm4(ah[mt], aoff + so + mt * 1280 + kk * 32);
                ldsm4(al[mt], aoff + so + 10240 + mt * 1280 + kk * 32);
            }
            {
                uint32_t bh[4][4];
#pragma unroll
                for (int g = 0; g < 4; g++) ldsm4(bh[g], boff + so + g * 1280 + kk * 32);
#pragma unroll
                for (int mt = 0; mt < 2; mt++)
#pragma unroll
                    for (int nt = 0; nt < 8; nt++) {
                        const int g = nt >> 1, o = nt & 1;
                        uint32_t bf[2] = {bh[g][o], bh[g][o + 2]};
                        mma16816(acc[mt][nt], ah[mt], bf);
                        mma16816(acc[mt][nt], al[mt], bf);
                    }
            }
            {
                uint32_t bl[4][4];
#pragma unroll
                for (int g = 0; g < 4; g++) ldsm4(bl[g], boff + so + 10240 + g * 1280 + kk * 32);
#pragma unroll
                for (int mt = 0; mt < 2; mt++)
#pragma unroll
                    for (int nt = 0; nt < 8; nt++) {
                        const int g = nt >> 1, o = nt & 1;
                        uint32_t bf[2] = {bl[g][o], bl[g][o + 2]};
                        mma16816(acc[mt][nt], ah[mt], bf);
                    }
            }
        }
        if (more) STORES((kt + 1) & 1);
        __syncthreads();
    }

    const int rb = m0 + wm * 32 + (lane >> 2);
    const int cb = n0 + wn * 64 + (lane & 3) * 2;
#pragma unroll
    for (int mt = 0; mt < 2; mt++)
#pragma unroll
        for (int nt = 0; nt < 8; nt++) {
            const int r0 = rb + mt * 16;
            const int c = cb + nt * 8;
            float2 v0 = make_float2(alpha * acc[mt][nt][0], alpha * acc[mt][nt][1]);
            float2 v1 = make_float2(alpha * acc[mt][nt][2], alpha * acc[mt][nt][3]);
            if (add) {
                float2 d0 = *(const float2*)(add + (size_t)r0 * ldc + c);
                float2 d1 = *(const float2*)(add + (size_t)(r0 + 8) * ldc + c);
                v0.x += d0.x; v0.y += d0.y; v1.x += d1.x; v1.y += d1.y;
            }
            *(float2*)(C + (size_t)r0 * ldc + c) = v0;
            *(float2*)(C + (size_t)(r0 + 8) * ldc + c) = v1;
        }
}

// =================================================================
// flash attention: one CTA per (head, 128-row q block). 8 warps,
// each warp owns 16 q rows. Split-bf16 QK^T and PV, online softmax.
// smem: Qh,Ql,Kh,Kl [128][136] bf16; VTh,VTl [128 d][136 s]; sid[128].
// =================================================================
#define FQH 0
#define FQL 34816
#define FKH 69632
#define FKL 104448
#define FVH 139264
#define FVL 174080
#define FSD 208896
#define FL_SMEM 209408

__global__ void __launch_bounds__(256, 1) flash_attn(
    const float* __restrict__ q, const float* __restrict__ k,
    const float* __restrict__ v, const int* __restrict__ sid,
    float* __restrict__ out) {
    extern __shared__ char sm[];
    const int z = blockIdx.x;
    const int ib = 15 - (z >> 4);   // descending size for LPT scheduling
    const int h = z & 15;
    const int kvh = h >> 1;
    const int tid = threadIdx.x, lane = tid & 31, w = tid >> 5;
    const uint32_t sb = smem_to_u32(sm);

    // ---- load Q tile (scaled) into smem hi/lo ----
    {
        const int r = tid >> 1, c0 = (tid & 1) * 64;
        const float* src = q + (size_t)(ib * 128 + r) * (H * D) + h * D + c0;
        char* dh = sm + FQH + r * 272 + c0 * 2;
        char* dl = sm + FQL + r * 272 + c0 * 2;
#pragma unroll
        for (int x = 0; x < 16; x++) {
            float4 a = *(const float4*)(src + x * 4);
            a.x *= SCALE; a.y *= SCALE; a.z *= SCALE; a.w *= SCALE;
            split_store(dh + x * 8, dl + x * 8, a);
        }
    }

    const int r0g = ib * 128 + w * 16 + (lane >> 2);   // global q row for c0/c1
    const int sid0 = sid[r0g], sid1 = sid[r0g + 8];

    float m0 = -1e30f, m1 = -1e30f, l0 = 0.f, l1 = 0.f;
    float oa[16][4];
#pragma unroll
    for (int i = 0; i < 16; i++)
#pragma unroll
        for (int j = 0; j < 4; j++) oa[i][j] = 0.f;

    const uint32_t arh = sb + FQH + (uint32_t)(w * 16 + (lane & 15)) * 272 + (uint32_t)(lane >> 4) * 16;
    const uint32_t arl = arh + (FQL - FQH);
    const int* sid_sm = (const int*)(sm + FSD);

    for (int jb = 0; jb <= ib; jb++) {
        __syncthreads();   // prior-iter smem reads done (also orders Q stores on iter 0)
        // ---- load K tile + transposed V tile + sid ----
        {
            const int r = tid >> 1, c0 = (tid & 1) * 64;
            const float* ks = k + (size_t)(jb * 128 + r) * (KVH * D) + kvh * D + c0;
            char* dh = sm + FKH + r * 272 + c0 * 2;
            char* dl = sm + FKL + r * 272 + c0 * 2;
#pragma unroll
            for (int x = 0; x < 16; x++) {
                float4 a = *(const float4*)(ks + x * 4);
                split_store(dh + x * 8, dl + x * 8, a);
            }
            const float* vs = v + (size_t)(jb * 128 + r) * (KVH * D) + kvh * D + c0;
#pragma unroll
            for (int x = 0; x < 16; x++) {
                float4 a = *(const float4*)(vs + x * 4);
                float av[4] = {a.x, a.y, a.z, a.w};
#pragma unroll
                for (int e = 0; e < 4; e++) {
                    const int d = c0 + x * 4 + e;
                    __nv_bfloat16 bh = __float2bfloat16(av[e]);
                    float lo = av[e] - __bfloat162float(bh);
                    __nv_bfloat16 bl = __float2bfloat16(lo);
                    *(uint16_t*)(sm + FVH + d * 272 + r * 2) = *(uint16_t*)&bh;
                    *(uint16_t*)(sm + FVL + d * 272 + r * 2) = *(uint16_t*)&bl;
                }
            }
            if (tid < 128) ((int*)(sm + FSD))[tid] = sid[jb * 128 + tid];
        }
        __syncthreads();

        // ---- S = Q @ K^T (3-term split) ----
        float s[16][4];
#pragma unroll
        for (int i = 0; i < 16; i++)
#pragma unroll
            for (int j = 0; j < 4; j++) s[i][j] = 0.f;

#pragma unroll
        for (int kk = 0; kk < 8; kk++) {
            uint32_t ah[4], al[4];
            ldsm4(ah, arh + kk * 32);
            ldsm4(al, arl + kk * 32);
#pragma unroll
            for (int ng = 0; ng < 8; ng++) {
                const uint32_t br = sb + FKH + (uint32_t)(ng * 16 + (lane & 15)) * 272
                                    + (uint32_t)(lane >> 4) * 16 + kk * 32;
                uint32_t bh[4], bl[4];
                ldsm4(bh, br);
                ldsm4(bl, br + (FKL - FKH));
#pragma unroll
                for (int o = 0; o < 2; o++) {
                    uint32_t bfh[2] = {bh[o], bh[o + 2]};
                    uint32_t bfl[2] = {bl[o], bl[o + 2]};
                    mma16816(s[ng * 2 + o], ah, bfh);
                    mma16816(s[ng * 2 + o], al, bfh);
                    mma16816(s[ng * 2 + o], ah, bfl);
                }
            }
        }

        // ---- mask: same sid && causal ----
        const int cloc = (lane & 3) * 2;
#pragma unroll
        for (int nt = 0; nt < 16; nt++) {
            const int c0l = nt * 8 + cloc;
            const int sc0 = sid_sm[c0l], sc1 = sid_sm[c0l + 1];
            const int c0gl = jb * 128 + c0l;
            if (!(sc0 == sid0 && c0gl <= r0g))          s[nt][0] = -1e30f;
            if (!(sc1 == sid0 && c0gl + 1 <= r0g))      s[nt][1] = -1e30f;
            if (!(sc0 == sid1 && c0gl <= r0g + 8))      s[nt][2] = -1e30f;
            if (!(sc1 == sid1 && c0gl + 1 <= r0g + 8))  s[nt][3] = -1e30f;
        }

        // ---- online softmax ----
        float tm0 = -1e30f, tm1 = -1e30f;
#pragma unroll
        for (int nt = 0; nt < 16; nt++) {
            tm0 = fmaxf(tm0, fmaxf(s[nt][0], s[nt][1]));
            tm1 = fmaxf(tm1, fmaxf(s[nt][2], s[nt][3]));
        }
        tm0 = fmaxf(tm0, __shfl_xor_sync(~0u, tm0, 1));
        tm0 = fmaxf(tm0, __shfl_xor_sync(~0u, tm0, 2));
        tm1 = fmaxf(tm1, __shfl_xor_sync(~0u, tm1, 1));
        tm1 = fmaxf(tm1, __shfl_xor_sync(~0u, tm1, 2));
        const float nm0 = fmaxf(m0, tm0), nm1 = fmaxf(m1, tm1);
        const float cf0 = __expf(m0 - nm0), cf1 = __expf(m1 - nm1);
        m0 = nm0; m1 = nm1;
        float rs0 = 0.f, rs1 = 0.f;
#pragma unroll
        for (int nt = 0; nt < 16; nt++) {
            float p0 = (s[nt][0] > -1e29f) ? __expf(s[nt][0] - nm0) : 0.f;
            float p1 = (s[nt][1] > -1e29f) ? __expf(s[nt][1] - nm0) : 0.f;
            float p2 = (s[nt][2] > -1e29f) ? __expf(s[nt][2] - nm1) : 0.f;
            float p3 = (s[nt][3] > -1e29f) ? __expf(s[nt][3] - nm1) : 0.f;
            s[nt][0] = p0; s[nt][1] = p1; s[nt][2] = p2; s[nt][3] = p3;
            rs0 += p0 + p1; rs1 += p2 + p3;
        }
        l0 = l0 * cf0 + rs0;
        l1 = l1 * cf1 + rs1;
#pragma unroll
        for (int nt = 0; nt < 16; nt++) {
            oa[nt][0] *= cf0; oa[nt][1] *= cf0;
            oa[nt][2] *= cf1; oa[nt][3] *= cf1;
        }

        // ---- O += P @ V (3-term split; P from register fragments) ----
#pragma unroll
        for (int kp = 0; kp < 8; kp++) {
            uint32_t pah[4], pal[4];
            {
                const float* t0 = s[kp * 2];
                const float* t1 = s[kp * 2 + 1];
                pah[0] = pack_bf16(t0[0], t0[1]);
                pah[1] = pack_bf16(t0[2], t0[3]);
                pah[2] = pack_bf16(t1[0], t1[1]);
                pah[3] = pack_bf16(t1[2], t1[3]);
#pragma unroll
                for (int u = 0; u < 4; u++) {
                    const float* tt = (u < 2) ? t0 : t1;
                    const int b = (u & 1) * 2;
                    float f0 = __uint_as_float(pah[u] << 16);
                    float f1 = __uint_as_float(pah[u] & 0xffff0000u);
                    pal[u] = pack_bf16(tt[b] - f0, tt[b + 1] - f1);
                }
            }
#pragma unroll
            for (int ng = 0; ng < 8; ng++) {
                const uint32_t br = sb + FVH + (uint32_t)(ng * 16 + (lane & 15)) * 272
                                    + (uint32_t)(lane >> 4) * 16 + kp * 32;
                uint32_t bh[4], bl[4];
                ldsm4(bh, br);
                ldsm4(bl, br + (FVL - FVH));
#pragma unroll
                for (int o = 0; o < 2; o++) {
                    uint32_t bfh[2] = {bh[o], bh[o + 2]};
                    uint32_t bfl[2] = {bl[o], bl[o + 2]};
                    mma16816(oa[ng * 2 + o], pah, bfh);
                    mma16816(oa[ng * 2 + o], pal, bfh);
                    mma16816(oa[ng * 2 + o], pah, bfl);
                }
            }
        }
    }

    // ---- epilogue: normalize and write ----
    l0 += __shfl_xor_sync(~0u, l0, 1); l0 += __shfl_xor_sync(~0u, l0, 2);
    l1 += __shfl_xor_sync(~0u, l1, 1); l1 += __shfl_xor_sync(~0u, l1, 2);
    const float i0 = 1.f / l0, i1 = 1.f / l1;
    float* o0 = out + (size_t)r0g * (H * D) + h * D + (lane & 3) * 2;
    float* o1 = out + (size_t)(r0g + 8) * (H * D) + h * D + (lane & 3) * 2;
#pragma unroll
    for (int nt = 0; nt < 16; nt++) {
        *(float2*)(o0 + nt * 8) = make_float2(oa[nt][0] * i0, oa[nt][1] * i0);
        *(float2*)(o1 + nt * 8) = make_float2(oa[nt][2] * i1, oa[nt][3] * i1);
    }
}

// ================= fp32 support kernels =================
__global__ void rmsnorm_kernel(const float* __restrict__ x, const float* __restrict__ w,
                               float* __restrict__ out, int dim) {
    int row = blockIdx.x;
    const float* xr = x + (size_t)row * dim;
    float ss = 0.f;
    for (int i = threadIdx.x; i < dim; i += blockDim.x) { float v = xr[i]; ss += v * v; }
    __shared__ float red[32];
    for (int o = 16; o; o >>= 1) ss += __shfl_xor_sync(~0u, ss, o);
    if ((threadIdx.x & 31) == 0) red[threadIdx.x >> 5] = ss;
    __syncthreads();
    if (threadIdx.x < 32) {
        float v = (threadIdx.x < (blockDim.x >> 5)) ? red[threadIdx.x] : 0.f;
        for (int o = 16; o; o >>= 1) v += __shfl_xor_sync(~0u, v, o);
        if (threadIdx.x == 0) red[0] = v;
    }
    __syncthreads();
    float inv = rsqrtf(red[0] / (float)dim + 1e-6f);
    for (int i = threadIdx.x; i < dim; i += blockDim.x)
        out[(size_t)row * dim + i] = xr[i] * inv * w[i];
}

__global__ void rope_kernel(float* __restrict__ q, float* __restrict__ k,
                            const int* __restrict__ pos) {
    int idx = blockIdx.x * blockDim.x + threadIdx.x;
    const int total = SEQ * (H + KVH) * 64;
    if (idx >= total) return;
    int j = idx & 63;
    int slot = (idx >> 6) % (H + KVH);
    int srow = idx / (64 * (H + KVH));
    float p = (float)pos[srow];
    float invf = __expf(-(float)j * (logf(10000.f) / 64.f));
    float ang = p * invf;
    float c = cosf(ang), sn = sinf(ang);
    float* base;
    if (slot < H) base = q + (size_t)srow * (H * D) + slot * D;
    else          base = k + (size_t)srow * (KVH * D) + (slot - H) * D;
    float x0 = base[j], x1 = base[j + 64];
    base[j]      = x0 * c - x1 * sn;
    base[j + 64] = x1 * c + x0 * sn;
}

__global__ void silu_mul_kernel(float* __restrict__ g, const float* __restrict__ u, size_t n) {
    size_t i = (size_t)blockIdx.x * blockDim.x + threadIdx.x;
    if (i < n) {
        float x = g[i];
        float s = 1.f / (1.f + __expf(-x));
        g[i] = x * s * u[i];
    }
}

extern "C" void kernel_launch(void* const* d_in, const int* in_sizes, int n_in,
                              void* d_out, int out_size) {
    const float* hs  = (const float*)d_in[0];
    const int*   sid = (const int*)d_in[1];
    const int*   pos = (const int*)d_in[2];
    const float* ln1 = (const float*)d_in[3];
    const float* wq  = (const float*)d_in[4];
    const float* wk  = (const float*)d_in[5];
    const float* wv  = (const float*)d_in[6];
    const float* wo  = (const float*)d_in[7];
    const float* ln2 = (const float*)d_in[8];
    const float* wg  = (const float*)d_in[9];
    const float* wu  = (const float*)d_in[10];
    const float* wd  = (const float*)d_in[11];
    float* out = (float*)d_out;

    float *xn, *q, *k, *v, *ao, *hb, *y, *gb, *ub;
    cudaGetSymbolAddress((void**)&xn, g_xn);
    cudaGetSymbolAddress((void**)&q,  g_q);
    cudaGetSymbolAddress((void**)&k,  g_k);
    cudaGetSymbolAddress((void**)&v,  g_v);
    cudaGetSymbolAddress((void**)&ao, g_ao);
    cudaGetSymbolAddress((void**)&hb, g_h);
    cudaGetSymbolAddress((void**)&y,  g_y);
    cudaGetSymbolAddress((void**)&gb, g_gate);
    cudaGetSymbolAddress((void**)&ub, g_up);

    cudaFuncSetAttribute(hmma_gemm, cudaFuncAttributeMaxDynamicSharedMemorySize, HM_SMEM);
    cudaFuncSetAttribute(flash_attn, cudaFuncAttributeMaxDynamicSharedMemorySize, FL_SMEM);

    // 1. pre-attention RMSNorm
    rmsnorm_kernel<<<SEQ, 256>>>(hs, ln1, xn, HID);

    // 2. QKV projections
    hmma_gemm<<<dim3(16, 16, 1), 256, HM_SMEM>>>(xn, HID, 0, wq, HID, 0, 0, q, H * D, 0, nullptr, 1.f, HID);
    hmma_gemm<<<dim3(8, 16, 1), 256, HM_SMEM>>>(xn, HID, 0, wk, HID, 0, 0, k, KVH * D, 0, nullptr, 1.f, HID);
    hmma_gemm<<<dim3(8, 16, 1), 256, HM_SMEM>>>(xn, HID, 0, wv, HID, 0, 0, v, KVH * D, 0, nullptr, 1.f, HID);

    // 3. RoPE
    rope_kernel<<<(SEQ * (H + KVH) * 64 + 255) / 256, 256>>>(q, k, pos);

    // 4. fused flash attention (same-sid & causal mask; window inactive at s=2048)
    flash_attn<<<256, 256, FL_SMEM>>>(q, k, v, sid, ao);

    // 5. h = resid + attn_out @ Wo^T
    hmma_gemm<<<dim3(16, 16, 1), 256, HM_SMEM>>>(ao, H * D, 0, wo, H * D, 0, 0, hb, HID, 0, hs, 1.f, H * D);

    // 6. post-attention RMSNorm
    rmsnorm_kernel<<<SEQ, 256>>>(hb, ln2, y, HID);

    // 7. MLP
    hmma_gemm<<<dim3(64, 16, 1), 256, HM_SMEM>>>(y, HID, 0, wg, HID, 0, 0, gb, INTERM, 0, nullptr, 1.f, HID);
    hmma_gemm<<<dim3(64, 16, 1), 256, HM_SMEM>>>(y, HID, 0, wu, HID, 0, 0, ub, INTERM, 0, nullptr, 1.f, HID);
    silu_mul_kernel<<<(SEQ * INTERM + 255) / 256, 256>>>(gb, ub, (size_t)SEQ * INTERM);
    hmma_gemm<<<dim3(16, 16, 1), 256, HM_SMEM>>>(gb, INTERM, 0, wd, INTERM, 0, 0, out, HID, 0, hb, 1.f, INTERM);
}

// round 5
// speedup vs baseline: 3.8099x; 1.3108x over previous
#include <cuda_runtime.h>
#include <cuda_bf16.h>
#include <cstdint>
#include <math.h>

#define SEQ 2048
#define H 16
#define KVH 8
#define D 128
#define HID 2048
#define INTERM 8192
#define SCALE 0.08838834764831845f

// ---------------- scratch (device globals) ----------------
__device__ float          g_qkv[SEQ * 4096];          // q | k | v merged, fp32
__device__ __nv_bfloat16  g_xnh[SEQ * HID],  g_xnl[SEQ * HID];
__device__ __nv_bfloat16  g_aoh[SEQ * 2048], g_aol[SEQ * 2048];
__device__ float          g_hb[SEQ * HID];
__device__ __nv_bfloat16  g_yh[SEQ * HID],   g_yl[SEQ * HID];
__device__ float          g_gu[SEQ * 16384];          // gate | up merged, fp32
__device__ __nv_bfloat16  g_gh[SEQ * INTERM], g_gl[SEQ * INTERM];
// split weights
__device__ __nv_bfloat16  g_wqkvh[4096 * 2048], g_wqkvl[4096 * 2048];
__device__ __nv_bfloat16  g_woh[2048 * 2048],   g_wol[2048 * 2048];
__device__ __nv_bfloat16  g_wguh[16384 * 2048], g_wgul[16384 * 2048];
__device__ __nv_bfloat16  g_wdh[2048 * 8192],   g_wdl[2048 * 8192];

// ================= helpers =================
__device__ __forceinline__ uint32_t smem_to_u32(const void* p) {
    uint32_t a;
    asm("{ .reg .u64 t; cvta.to.shared.u64 t, %1; cvt.u32.u64 %0, t; }" : "=r"(a) : "l"(p));
    return a;
}
__device__ __forceinline__ uint32_t pack_bf16(float lo, float hi) {
    uint32_t r;
    asm("cvt.rn.satfinite.bf16x2.f32 %0, %1, %2;" : "=r"(r) : "f"(hi), "f"(lo));
    return r;
}
__device__ __forceinline__ void ldsm4(uint32_t* r, uint32_t addr) {
    asm volatile("ldmatrix.sync.aligned.m8n8.x4.shared.b16 {%0,%1,%2,%3}, [%4];"
                 : "=r"(r[0]), "=r"(r[1]), "=r"(r[2]), "=r"(r[3]) : "r"(addr));
}
__device__ __forceinline__ void mma16816(float* c, const uint32_t* a, const uint32_t* b) {
    asm volatile(
        "mma.sync.aligned.m16n8k16.row.col.f32.bf16.bf16.f32 "
        "{%0,%1,%2,%3}, {%4,%5,%6,%7}, {%8,%9}, {%0,%1,%2,%3};"
        : "+f"(c[0]), "+f"(c[1]), "+f"(c[2]), "+f"(c[3])
        : "r"(a[0]), "r"(a[1]), "r"(a[2]), "r"(a[3]), "r"(b[0]), "r"(b[1]));
}
__device__ __forceinline__ void split_store(char* dh, char* dl, float4 a) {
    uint32_t h01 = pack_bf16(a.x, a.y), h23 = pack_bf16(a.z, a.w);
    float f0 = __uint_as_float(h01 << 16), f1 = __uint_as_float(h01 & 0xffff0000u);
    float f2 = __uint_as_float(h23 << 16), f3 = __uint_as_float(h23 & 0xffff0000u);
    *(uint2*)dh = make_uint2(h01, h23);
    *(uint2*)dl = make_uint2(pack_bf16(a.x - f0, a.y - f1), pack_bf16(a.z - f2, a.w - f3));
}
#define CP16(dst, src) \
    asm volatile("cp.async.ca.shared.global [%0], [%1], 16;" :: "r"(dst), "l"(src) : "memory")
#define CPCOMMIT() asm volatile("cp.async.commit_group;" ::: "memory")
#define CPWAIT0()  asm volatile("cp.async.wait_group 0;" ::: "memory")

// =================================================================
// hmma_gemm: C[M,N] = alpha * Ahl[M,K] @ Bhl[N,K]^T (+ add).
// Pre-split bf16 hi/lo inputs, cp.async 2-stage pipeline.
// 128x128 tile, K chunk 32, 256 threads (8 warps: 4Mx2N, warp 32x64).
// smem/stage: Ah[128][40] @0, Al @10240, Bh @20480, Bl @30720.
// =================================================================
#define STAGE_BYTES 40960
#define HM_SMEM (2 * STAGE_BYTES)

__global__ void __launch_bounds__(256, 2) hmma_gemm(
    const __nv_bfloat16* __restrict__ Ah, const __nv_bfloat16* __restrict__ Al,
    const __nv_bfloat16* __restrict__ Bh, const __nv_bfloat16* __restrict__ Bl,
    float* __restrict__ C, int ldc,
    const float* __restrict__ add, float alpha, int K) {
    extern __shared__ char sm[];
    const int tid = threadIdx.x;
    const int lane = tid & 31, wid = tid >> 5;
    const int wm = wid >> 1, wn = wid & 1;
    const int m0 = blockIdx.y * 128, n0 = blockIdx.x * 128;

    const uint32_t sb = smem_to_u32(sm);
    const int lrow = lane & 15;
    const uint32_t lcol = (uint32_t)(lane >> 4) * 16;
    const uint32_t aoff = sb + (uint32_t)(wm * 32 + lrow) * 80 + lcol;
    const uint32_t boff = sb + 20480 + (uint32_t)(wn * 64 + lrow) * 80 + lcol;

    // loader: thread t -> row t>>1, 16-bf16 half (t&1)
    const int r = tid >> 1, hs = (tid & 1) * 16;
    const char* agh = (const char*)(Ah + (size_t)(m0 + r) * K + hs);
    const char* agl = (const char*)(Al + (size_t)(m0 + r) * K + hs);
    const char* bgh = (const char*)(Bh + (size_t)(n0 + r) * K + hs);
    const char* bgl = (const char*)(Bl + (size_t)(n0 + r) * K + hs);
    const uint32_t sA = (uint32_t)r * 80 + (uint32_t)hs * 2;

#define PREFETCH(st, kt) do { \
    const uint32_t _d = sb + (uint32_t)(st) * STAGE_BYTES + sA; \
    const size_t _o = (size_t)(kt) * 64; \
    CP16(_d,             agh + _o); CP16(_d + 16,         agh + _o + 16); \
    CP16(_d + 10240,     agl + _o); CP16(_d + 10240 + 16, agl + _o + 16); \
    CP16(_d + 20480,     bgh + _o); CP16(_d + 20480 + 16, bgh + _o + 16); \
    CP16(_d + 30720,     bgl + _o); CP16(_d + 30720 + 16, bgl + _o + 16); \
    CPCOMMIT(); \
} while (0)

    float acc[2][8][4];
#pragma unroll
    for (int i = 0; i < 2; i++)
#pragma unroll
        for (int j = 0; j < 8; j++)
#pragma unroll
            for (int l = 0; l < 4; l++) acc[i][j][l] = 0.f;

    const int nk = K >> 5;
    PREFETCH(0, 0);

    for (int kt = 0; kt < nk; kt++) {
        const int b = kt & 1;
        const uint32_t so = (uint32_t)b * STAGE_BYTES;
        CPWAIT0();
        __syncthreads();
        if (kt + 1 < nk) PREFETCH(b ^ 1, kt + 1);

#pragma unroll
        for (int kk = 0; kk < 2; kk++) {
            uint32_t ah[2][4], al[2][4];
#pragma unroll
            for (int mt = 0; mt < 2; mt++) {
                ldsm4(ah[mt], aoff + so + mt * 1280 + kk * 32);
                ldsm4(al[mt], aoff + so + 10240 + mt * 1280 + kk * 32);
            }
            {
                uint32_t bh[4][4];
#pragma unroll
                for (int g = 0; g < 4; g++) ldsm4(bh[g], boff + so + g * 1280 + kk * 32);
#pragma unroll
                for (int mt = 0; mt < 2; mt++)
#pragma unroll
                    for (int nt = 0; nt < 8; nt++) {
                        const int g = nt >> 1, o = nt & 1;
                        uint32_t bf[2] = {bh[g][o], bh[g][o + 2]};
                        mma16816(acc[mt][nt], ah[mt], bf);
                        mma16816(acc[mt][nt], al[mt], bf);
                    }
            }
            {
                uint32_t bl[4][4];
#pragma unroll
                for (int g = 0; g < 4; g++) ldsm4(bl[g], boff + so + 10240 + g * 1280 + kk * 32);
#pragma unroll
                for (int mt = 0; mt < 2; mt++)
#pragma unroll
                    for (int nt = 0; nt < 8; nt++) {
                        const int g = nt >> 1, o = nt & 1;
                        uint32_t bf[2] = {bl[g][o], bl[g][o + 2]};
                        mma16816(acc[mt][nt], ah[mt], bf);
                    }
            }
        }
        __syncthreads();   // all reads of stage b done before it is overwritten
    }

    const int rb = m0 + wm * 32 + (lane >> 2);
    const int cb = n0 + wn * 64 + (lane & 3) * 2;
#pragma unroll
    for (int mt = 0; mt < 2; mt++)
#pragma unroll
        for (int nt = 0; nt < 8; nt++) {
            const int r0 = rb + mt * 16;
            const int c = cb + nt * 8;
            float2 v0 = make_float2(alpha * acc[mt][nt][0], alpha * acc[mt][nt][1]);
            float2 v1 = make_float2(alpha * acc[mt][nt][2], alpha * acc[mt][nt][3]);
            if (add) {
                float2 d0 = *(const float2*)(add + (size_t)r0 * ldc + c);
                float2 d1 = *(const float2*)(add + (size_t)(r0 + 8) * ldc + c);
                v0.x += d0.x; v0.y += d0.y; v1.x += d1.x; v1.y += d1.y;
            }
            *(float2*)(C + (size_t)r0 * ldc + c) = v0;
            *(float2*)(C + (size_t)(r0 + 8) * ldc + c) = v1;
        }
}

// =================================================================
// flash attention on merged qkv buffer (row stride 4096:
// q at col h*128, k at 2048+kvh*128, v at 3072+kvh*128).
// Epilogue writes split bf16 attention output.
// =================================================================
#define FQH 0
#define FQL 34816
#define FKH 69632
#define FKL 104448
#define FVH 139264
#define FVL 174080
#define FSD 208896
#define FL_SMEM 209408

__global__ void __launch_bounds__(256, 1) flash_attn(
    const float* __restrict__ qkv, const int* __restrict__ sid,
    __nv_bfloat16* __restrict__ aoh, __nv_bfloat16* __restrict__ aol) {
    extern __shared__ char sm[];
    const int z = blockIdx.x;
    const int ib = 15 - (z >> 4);   // descending size for LPT scheduling
    const int h = z & 15;
    const int kvh = h >> 1;
    const int tid = threadIdx.x, lane = tid & 31, w = tid >> 5;
    const uint32_t sb = smem_to_u32(sm);

    // ---- load Q tile (scaled) into smem hi/lo ----
    {
        const int r = tid >> 1, c0 = (tid & 1) * 64;
        const float* src = qkv + (size_t)(ib * 128 + r) * 4096 + h * D + c0;
        char* dh = sm + FQH + r * 272 + c0 * 2;
        char* dl = sm + FQL + r * 272 + c0 * 2;
#pragma unroll
        for (int x = 0; x < 16; x++) {
            float4 a = *(const float4*)(src + x * 4);
            a.x *= SCALE; a.y *= SCALE; a.z *= SCALE; a.w *= SCALE;
            split_store(dh + x * 8, dl + x * 8, a);
        }
    }

    const int r0g = ib * 128 + w * 16 + (lane >> 2);
    const int sid0 = sid[r0g], sid1 = sid[r0g + 8];

    float m0 = -1e30f, m1 = -1e30f, l0 = 0.f, l1 = 0.f;
    float oa[16][4];
#pragma unroll
    for (int i = 0; i < 16; i++)
#pragma unroll
        for (int j = 0; j < 4; j++) oa[i][j] = 0.f;

    const uint32_t arh = sb + FQH + (uint32_t)(w * 16 + (lane & 15)) * 272 + (uint32_t)(lane >> 4) * 16;
    const uint32_t arl = arh + (FQL - FQH);
    const int* sid_sm = (const int*)(sm + FSD);

    for (int jb = 0; jb <= ib; jb++) {
        __syncthreads();
        {
            const int r = tid >> 1, c0 = (tid & 1) * 64;
            const float* ks = qkv + (size_t)(jb * 128 + r) * 4096 + 2048 + kvh * D + c0;
            char* dh = sm + FKH + r * 272 + c0 * 2;
            char* dl = sm + FKL + r * 272 + c0 * 2;
#pragma unroll
            for (int x = 0; x < 16; x++) {
                float4 a = *(const float4*)(ks + x * 4);
                split_store(dh + x * 8, dl + x * 8, a);
            }
            const float* vs = qkv + (size_t)(jb * 128 + r) * 4096 + 3072 + kvh * D + c0;
#pragma unroll
            for (int x = 0; x < 16; x++) {
                float4 a = *(const float4*)(vs + x * 4);
                float av[4] = {a.x, a.y, a.z, a.w};
#pragma unroll
                for (int e = 0; e < 4; e++) {
                    const int d = c0 + x * 4 + e;
                    __nv_bfloat16 bh = __float2bfloat16(av[e]);
                    float lo = av[e] - __bfloat162float(bh);
                    __nv_bfloat16 bl = __float2bfloat16(lo);
                    *(uint16_t*)(sm + FVH + d * 272 + r * 2) = *(uint16_t*)&bh;
                    *(uint16_t*)(sm + FVL + d * 272 + r * 2) = *(uint16_t*)&bl;
                }
            }
            if (tid < 128) ((int*)(sm + FSD))[tid] = sid[jb * 128 + tid];
        }
        __syncthreads();

        float s[16][4];
#pragma unroll
        for (int i = 0; i < 16; i++)
#pragma unroll
            for (int j = 0; j < 4; j++) s[i][j] = 0.f;

#pragma unroll
        for (int kk = 0; kk < 8; kk++) {
            uint32_t ah[4], al[4];
            ldsm4(ah, arh + kk * 32);
            ldsm4(al, arl + kk * 32);
#pragma unroll
            for (int ng = 0; ng < 8; ng++) {
                const uint32_t br = sb + FKH + (uint32_t)(ng * 16 + (lane & 15)) * 272
                                    + (uint32_t)(lane >> 4) * 16 + kk * 32;
                uint32_t bh[4], bl[4];
                ldsm4(bh, br);
                ldsm4(bl, br + (FKL - FKH));
#pragma unroll
                for (int o = 0; o < 2; o++) {
                    uint32_t bfh[2] = {bh[o], bh[o + 2]};
                    uint32_t bfl[2] = {bl[o], bl[o + 2]};
                    mma16816(s[ng * 2 + o], ah, bfh);
                    mma16816(s[ng * 2 + o], al, bfh);
                    mma16816(s[ng * 2 + o], ah, bfl);
                }
            }
        }

        const int cloc = (lane & 3) * 2;
#pragma unroll
        for (int nt = 0; nt < 16; nt++) {
            const int c0l = nt * 8 + cloc;
            const int sc0 = sid_sm[c0l], sc1 = sid_sm[c0l + 1];
            const int c0gl = jb * 128 + c0l;
            if (!(sc0 == sid0 && c0gl <= r0g))          s[nt][0] = -1e30f;
            if (!(sc1 == sid0 && c0gl + 1 <= r0g))      s[nt][1] = -1e30f;
            if (!(sc0 == sid1 && c0gl <= r0g + 8))      s[nt][2] = -1e30f;
            if (!(sc1 == sid1 && c0gl + 1 <= r0g + 8))  s[nt][3] = -1e30f;
        }

        float tm0 = -1e30f, tm1 = -1e30f;
#pragma unroll
        for (int nt = 0; nt < 16; nt++) {
            tm0 = fmaxf(tm0, fmaxf(s[nt][0], s[nt][1]));
            tm1 = fmaxf(tm1, fmaxf(s[nt][2], s[nt][3]));
        }
        tm0 = fmaxf(tm0, __shfl_xor_sync(~0u, tm0, 1));
        tm0 = fmaxf(tm0, __shfl_xor_sync(~0u, tm0, 2));
        tm1 = fmaxf(tm1, __shfl_xor_sync(~0u, tm1, 1));
        tm1 = fmaxf(tm1, __shfl_xor_sync(~0u, tm1, 2));
        const float nm0 = fmaxf(m0, tm0), nm1 = fmaxf(m1, tm1);
        const float cf0 = __expf(m0 - nm0), cf1 = __expf(m1 - nm1);
        m0 = nm0; m1 = nm1;
        float rs0 = 0.f, rs1 = 0.f;
#pragma unroll
        for (int nt = 0; nt < 16; nt++) {
            float p0 = (s[nt][0] > -1e29f) ? __expf(s[nt][0] - nm0) : 0.f;
            float p1 = (s[nt][1] > -1e29f) ? __expf(s[nt][1] - nm0) : 0.f;
            float p2 = (s[nt][2] > -1e29f) ? __expf(s[nt][2] - nm1) : 0.f;
            float p3 = (s[nt][3] > -1e29f) ? __expf(s[nt][3] - nm1) : 0.f;
            s[nt][0] = p0; s[nt][1] = p1; s[nt][2] = p2; s[nt][3] = p3;
            rs0 += p0 + p1; rs1 += p2 + p3;
        }
        l0 = l0 * cf0 + rs0;
        l1 = l1 * cf1 + rs1;
#pragma unroll
        for (int nt = 0; nt < 16; nt++) {
            oa[nt][0] *= cf0; oa[nt][1] *= cf0;
            oa[nt][2] *= cf1; oa[nt][3] *= cf1;
        }

#pragma unroll
        for (int kp = 0; kp < 8; kp++) {
            uint32_t pah[4], pal[4];
            {
                const float* t0 = s[kp * 2];
                const float* t1 = s[kp * 2 + 1];
                pah[0] = pack_bf16(t0[0], t0[1]);
                pah[1] = pack_bf16(t0[2], t0[3]);
                pah[2] = pack_bf16(t1[0], t1[1]);
                pah[3] = pack_bf16(t1[2], t1[3]);
#pragma unroll
                for (int u = 0; u < 4; u++) {
                    const float* tt = (u < 2) ? t0 : t1;
                    const int b = (u & 1) * 2;
                    float f0 = __uint_as_float(pah[u] << 16);
                    float f1 = __uint_as_float(pah[u] & 0xffff0000u);
                    pal[u] = pack_bf16(tt[b] - f0, tt[b + 1] - f1);
                }
            }
#pragma unroll
            for (int ng = 0; ng < 8; ng++) {
                const uint32_t br = sb + FVH + (uint32_t)(ng * 16 + (lane & 15)) * 272
                                    + (uint32_t)(lane >> 4) * 16 + kp * 32;
                uint32_t bh[4], bl[4];
                ldsm4(bh, br);
                ldsm4(bl, br + (FVL - FVH));
#pragma unroll
                for (int o = 0; o < 2; o++) {
                    uint32_t bfh[2] = {bh[o], bh[o + 2]};
                    uint32_t bfl[2] = {bl[o], bl[o + 2]};
                    mma16816(oa[ng * 2 + o], pah, bfh);
                    mma16816(oa[ng * 2 + o], pal, bfh);
                    mma16816(oa[ng * 2 + o], pah, bfl);
                }
            }
        }
    }

    // ---- epilogue: normalize and write split bf16 ----
    l0 += __shfl_xor_sync(~0u, l0, 1); l0 += __shfl_xor_sync(~0u, l0, 2);
    l1 += __shfl_xor_sync(~0u, l1, 1); l1 += __shfl_xor_sync(~0u, l1, 2);
    const float i0 = 1.f / l0, i1 = 1.f / l1;
    const int cbase = h * D + (lane & 3) * 2;
    uint32_t* oh0 = (uint32_t*)aoh + (((size_t)r0g * 2048 + cbase) >> 1);
    uint32_t* ol0 = (uint32_t*)aol + (((size_t)r0g * 2048 + cbase) >> 1);
    uint32_t* oh1 = (uint32_t*)aoh + (((size_t)(r0g + 8) * 2048 + cbase) >> 1);
    uint32_t* ol1 = (uint32_t*)aol + (((size_t)(r0g + 8) * 2048 + cbase) >> 1);
#pragma unroll
    for (int nt = 0; nt < 16; nt++) {
        float a0 = oa[nt][0] * i0, a1 = oa[nt][1] * i0;
        float a2 = oa[nt][2] * i1, a3 = oa[nt][3] * i1;
        uint32_t h0 = pack_bf16(a0, a1), h1 = pack_bf16(a2, a3);
        float f0 = __uint_as_float(h0 << 16), f1 = __uint_as_float(h0 & 0xffff0000u);
        float f2 = __uint_as_float(h1 << 16), f3 = __uint_as_float(h1 & 0xffff0000u);
        oh0[nt * 4] = h0; ol0[nt * 4] = pack_bf16(a0 - f0, a1 - f1);
        oh1[nt * 4] = h1; ol1[nt * 4] = pack_bf16(a2 - f2, a3 - f3);
    }
}

// ================= elementwise kernels =================
__global__ void split_kernel(const float* __restrict__ in, __nv_bfloat16* __restrict__ oh,
                             __nv_bfloat16* __restrict__ ol, int n2) {
    int i = blockIdx.x * blockDim.x + threadIdx.x;
    if (i >= n2) return;
    float2 a = ((const float2*)in)[i];
    uint32_t h = pack_bf16(a.x, a.y);
    float f0 = __uint_as_float(h << 16), f1 = __uint_as_float(h & 0xffff0000u);
    ((uint32_t*)oh)[i] = h;
    ((uint32_t*)ol)[i] = pack_bf16(a.x - f0, a.y - f1);
}

__global__ void rmsnorm_split(const float* __restrict__ x, const float* __restrict__ w,
                              __nv_bfloat16* __restrict__ oh, __nv_bfloat16* __restrict__ ol,
                              int dim) {
    int row = blockIdx.x;
    const float* xr = x + (size_t)row * dim;
    float ss = 0.f;
    for (int i = threadIdx.x; i < dim; i += blockDim.x) { float v = xr[i]; ss += v * v; }
    __shared__ float red[32];
    for (int o = 16; o; o >>= 1) ss += __shfl_xor_sync(~0u, ss, o);
    if ((threadIdx.x & 31) == 0) red[threadIdx.x >> 5] = ss;
    __syncthreads();
    if (threadIdx.x < 32) {
        float v = (threadIdx.x < (blockDim.x >> 5)) ? red[threadIdx.x] : 0.f;
        for (int o = 16; o; o >>= 1) v += __shfl_xor_sync(~0u, v, o);
        if (threadIdx.x == 0) red[0] = v;
    }
    __syncthreads();
    float inv = rsqrtf(red[0] / (float)dim + 1e-6f);
    for (int i = threadIdx.x * 2; i < dim; i += blockDim.x * 2) {
        float v0 = xr[i] * inv * w[i];
        float v1 = xr[i + 1] * inv * w[i + 1];
        uint32_t h = pack_bf16(v0, v1);
        float f0 = __uint_as_float(h << 16), f1 = __uint_as_float(h & 0xffff0000u);
        ((uint32_t*)oh)[((size_t)row * dim + i) >> 1] = h;
        ((uint32_t*)ol)[((size_t)row * dim + i) >> 1] = pack_bf16(v0 - f0, v1 - f1);
    }
}

__global__ void rope_kernel(float* __restrict__ qkv, const int* __restrict__ pos) {
    int idx = blockIdx.x * blockDim.x + threadIdx.x;
    const int total = SEQ * (H + KVH) * 64;
    if (idx >= total) return;
    int j = idx & 63;
    int slot = (idx >> 6) % (H + KVH);
    int srow = idx / (64 * (H + KVH));
    float p = (float)pos[srow];
    float invf = __expf(-(float)j * (logf(10000.f) / 64.f));
    float ang = p * invf;
    float c = cosf(ang), sn = sinf(ang);
    float* base = qkv + (size_t)srow * 4096 +
                  (slot < H ? slot * D : 2048 + (slot - H) * D);
    float x0 = base[j], x1 = base[j + 64];
    base[j]      = x0 * c - x1 * sn;
    base[j + 64] = x1 * c + x0 * sn;
}

__global__ void silu_mul_split(const float* __restrict__ gu,
                               __nv_bfloat16* __restrict__ oh, __nv_bfloat16* __restrict__ ol) {
    size_t i = (size_t)blockIdx.x * blockDim.x + threadIdx.x;   // pair index
    if (i >= (size_t)SEQ * INTERM / 2) return;
    int row = (int)(i / (INTERM / 2));
    int cp = (int)(i % (INTERM / 2));
    const float* gr = gu + (size_t)row * 16384;
    float g0 = gr[cp * 2], g1 = gr[cp * 2 + 1];
    float u0 = gr[8192 + cp * 2], u1 = gr[8192 + cp * 2 + 1];
    float v0 = g0 / (1.f + __expf(-g0)) * u0;
    float v1 = g1 / (1.f + __expf(-g1)) * u1;
    uint32_t h = pack_bf16(v0, v1);
    float f0 = __uint_as_float(h << 16), f1 = __uint_as_float(h & 0xffff0000u);
    ((uint32_t*)oh)[i] = h;
    ((uint32_t*)ol)[i] = pack_bf16(v0 - f0, v1 - f1);
}

extern "C" void kernel_launch(void* const* d_in, const int* in_sizes, int n_in,
                              void* d_out, int out_size) {
    const float* hs  = (const float*)d_in[0];
    const int*   sid = (const int*)d_in[1];
    const int*   pos = (const int*)d_in[2];
    const float* ln1 = (const float*)d_in[3];
    const float* wq  = (const float*)d_in[4];
    const float* wk  = (const float*)d_in[5];
    const float* wv  = (const float*)d_in[6];
    const float* wo  = (const float*)d_in[7];
    const float* ln2 = (const float*)d_in[8];
    const float* wg  = (const float*)d_in[9];
    const float* wu  = (const float*)d_in[10];
    const float* wd  = (const float*)d_in[11];
    float* out = (float*)d_out;

    float *qkv, *hb, *gu;
    __nv_bfloat16 *xnh, *xnl, *aoh, *aol, *yh, *yl, *gh, *gl;
    __nv_bfloat16 *wqkvh, *wqkvl, *woh, *wol, *wguh, *wgul, *wdh, *wdl;
    cudaGetSymbolAddress((void**)&qkv,   g_qkv);
    cudaGetSymbolAddress((void**)&hb,    g_hb);
    cudaGetSymbolAddress((void**)&gu,    g_gu);
    cudaGetSymbolAddress((void**)&xnh,   g_xnh);  cudaGetSymbolAddress((void**)&xnl, g_xnl);
    cudaGetSymbolAddress((void**)&aoh,   g_aoh);  cudaGetSymbolAddress((void**)&aol, g_aol);
    cudaGetSymbolAddress((void**)&yh,    g_yh);   cudaGetSymbolAddress((void**)&yl,  g_yl);
    cudaGetSymbolAddress((void**)&gh,    g_gh);   cudaGetSymbolAddress((void**)&gl,  g_gl);
    cudaGetSymbolAddress((void**)&wqkvh, g_wqkvh); cudaGetSymbolAddress((void**)&wqkvl, g_wqkvl);
    cudaGetSymbolAddress((void**)&woh,   g_woh);   cudaGetSymbolAddress((void**)&wol,   g_wol);
    cudaGetSymbolAddress((void**)&wguh,  g_wguh);  cudaGetSymbolAddress((void**)&wgul,  g_wgul);
    cudaGetSymbolAddress((void**)&wdh,   g_wdh);   cudaGetSymbolAddress((void**)&wdl,   g_wdl);

    cudaFuncSetAttribute(hmma_gemm, cudaFuncAttributeMaxDynamicSharedMemorySize, HM_SMEM);
    cudaFuncSetAttribute(flash_attn, cudaFuncAttributeMaxDynamicSharedMemorySize, FL_SMEM);

    // 0. split all weights to bf16 hi/lo (wq|wk|wv merged; wg|wu merged)
    split_kernel<<<(2048 * 2048 / 2 + 255) / 256, 256>>>(wq, wqkvh, wqkvl, 2048 * 2048 / 2);
    split_kernel<<<(1024 * 2048 / 2 + 255) / 256, 256>>>(wk, wqkvh + 2048 * 2048, wqkvl + 2048 * 2048, 1024 * 2048 / 2);
    split_kernel<<<(1024 * 2048 / 2 + 255) / 256, 256>>>(wv, wqkvh + 3072 * 2048, wqkvl + 3072 * 2048, 1024 * 2048 / 2);
    split_kernel<<<(2048 * 2048 / 2 + 255) / 256, 256>>>(wo, woh, wol, 2048 * 2048 / 2);
    split_kernel<<<(8192 * 2048 / 2 + 255) / 256, 256>>>(wg, wguh, wgul, 8192 * 2048 / 2);
    split_kernel<<<(8192 * 2048 / 2 + 255) / 256, 256>>>(wu, wguh + 8192 * 2048, wgul + 8192 * 2048, 8192 * 2048 / 2);
    split_kernel<<<(2048 * 8192 / 2 + 255) / 256, 256>>>(wd, wdh, wdl, 2048 * 8192 / 2);

    // 1. pre-attention RMSNorm (split output)
    rmsnorm_split<<<SEQ, 256>>>(hs, ln1, xnh, xnl, HID);

    // 2. merged QKV projection -> qkv[2048][4096]
    hmma_gemm<<<dim3(32, 16), 256, HM_SMEM>>>(xnh, xnl, wqkvh, wqkvl, qkv, 4096, nullptr, 1.f, HID);

    // 3. RoPE on q,k inside merged buffer
    rope_kernel<<<(SEQ * (H + KVH) * 64 + 255) / 256, 256>>>(qkv, pos);

    // 4. fused flash attention -> split bf16 ao
    flash_attn<<<256, 256, FL_SMEM>>>(qkv, sid, aoh, aol);

    // 5. h = resid + attn_out @ Wo^T
    hmma_gemm<<<dim3(16, 16), 256, HM_SMEM>>>(aoh, aol, woh, wol, hb, HID, hs, 1.f, 2048);

    // 6. post-attention RMSNorm (split output)
    rmsnorm_split<<<SEQ, 256>>>(hb, ln2, yh, yl, HID);

    // 7. merged gate|up projection -> gu[2048][16384]
    hmma_gemm<<<dim3(128, 16), 256, HM_SMEM>>>(yh, yl, wguh, wgul, gu, 16384, nullptr, 1.f, HID);

    // 8. silu(gate)*up -> split bf16
    silu_mul_split<<<(SEQ * INTERM / 2 + 255) / 256, 256>>>(gu, gh, gl);

    // 9. down projection + residual -> out
    hmma_gemm<<<dim3(16, 16), 256, HM_SMEM>>>(gh, gl, wdh, wdl, out, HID, hb, 1.f, INTERM);
}

// round 6
// speedup vs baseline: 4.7859x; 1.2562x over previous
#include <cuda_runtime.h>
#include <cuda_fp16.h>
#include <cstdint>
#include <math.h>

#define SEQ 2048
#define H 16
#define KVH 8
#define D 128
#define HID 2048
#define INTERM 8192
#define SCALE 0.08838834764831845f

// ---------------- scratch (device globals) ----------------
__device__ float  g_qkv[SEQ * 4096];            // q|k|v fp32 from GEMM
__device__ __half g_xnh[SEQ * HID], g_xnl[SEQ * HID];
__device__ __half g_qh[SEQ * 2048], g_ql[SEQ * 2048];
__device__ __half g_kh[SEQ * 1024], g_vh[SEQ * 1024];
__device__ __half g_aoh[SEQ * 2048], g_aol[SEQ * 2048];
__device__ float  g_hb[SEQ * HID];
__device__ __half g_yh[SEQ * HID], g_yl[SEQ * HID];
__device__ float  g_gu[SEQ * 16384];            // gate|up fp32
__device__ __half g_gh[SEQ * INTERM], g_gl[SEQ * INTERM];
// weights: fp16 hi only (B operands)
__device__ __half g_wqkvh[4096 * 2048];
__device__ __half g_woh[2048 * 2048];
__device__ __half g_wguh[16384 * 2048];
__device__ __half g_wdh[2048 * 8192];

// ================= helpers =================
__device__ __forceinline__ uint32_t smem_to_u32(const void* p) {
    uint32_t a;
    asm("{ .reg .u64 t; cvta.to.shared.u64 t, %1; cvt.u32.u64 %0, t; }" : "=r"(a) : "l"(p));
    return a;
}
__device__ __forceinline__ uint32_t pack_h2(float a, float b) {
    __half2 h = __floats2half2_rn(a, b);
    return *reinterpret_cast<uint32_t*>(&h);
}
__device__ __forceinline__ void split2_h(float a, float b, uint32_t& hi, uint32_t& lo) {
    __half ha = __float2half_rn(a), hb = __float2half_rn(b);
    hi = ((uint32_t)*(uint16_t*)&hb << 16) | *(uint16_t*)&ha;
    lo = pack_h2(a - __half2float(ha), b - __half2float(hb));
}
__device__ __forceinline__ void ldsm4(uint32_t* r, uint32_t addr) {
    asm volatile("ldmatrix.sync.aligned.m8n8.x4.shared.b16 {%0,%1,%2,%3}, [%4];"
                 : "=r"(r[0]), "=r"(r[1]), "=r"(r[2]), "=r"(r[3]) : "r"(addr));
}
__device__ __forceinline__ void ldsm4t(uint32_t* r, uint32_t addr) {
    asm volatile("ldmatrix.sync.aligned.m8n8.x4.trans.shared.b16 {%0,%1,%2,%3}, [%4];"
                 : "=r"(r[0]), "=r"(r[1]), "=r"(r[2]), "=r"(r[3]) : "r"(addr));
}
__device__ __forceinline__ void mma16816(float* c, const uint32_t* a, const uint32_t* b) {
    asm volatile(
        "mma.sync.aligned.m16n8k16.row.col.f32.f16.f16.f32 "
        "{%0,%1,%2,%3}, {%4,%5,%6,%7}, {%8,%9}, {%0,%1,%2,%3};"
        : "+f"(c[0]), "+f"(c[1]), "+f"(c[2]), "+f"(c[3])
        : "r"(a[0]), "r"(a[1]), "r"(a[2]), "r"(a[3]), "r"(b[0]), "r"(b[1]));
}
#define CP16(dst, src) \
    asm volatile("cp.async.cg.shared.global [%0], [%1], 16;" :: "r"(dst), "l"(src) : "memory")
#define CPCOMMIT() asm volatile("cp.async.commit_group;" ::: "memory")
#define CPWAIT0()  asm volatile("cp.async.wait_group 0;" ::: "memory")
#define CPWAIT1()  asm volatile("cp.async.wait_group 1;" ::: "memory")

// =================================================================
// hmma_gemm: C[M,N] = alpha * (Ah+Al)[M,K] @ Bh[N,K]^T (+ add).
// fp16 2-term, 3-stage cp.async. 128x128 tile, K chunk 32,
// 256 threads (8 warps 4Mx2N). stage: Ah@0 Al@10240 Bh@20480 (30720 B).
// =================================================================
#define STG 30720
#define HM_SMEM (3 * STG)

__global__ void __launch_bounds__(256, 2) hmma_gemm(
    const __half* __restrict__ Ah, const __half* __restrict__ Al,
    const __half* __restrict__ Bh,
    float* __restrict__ C, int ldc,
    const float* __restrict__ add, float alpha, int K) {
    extern __shared__ char sm[];
    const int tid = threadIdx.x;
    const int lane = tid & 31, wid = tid >> 5;
    const int wm = wid >> 1, wn = wid & 1;
    const int m0 = blockIdx.y * 128, n0 = blockIdx.x * 128;

    const uint32_t sb = smem_to_u32(sm);
    const uint32_t aoff = sb + (uint32_t)(wm * 32 + (lane & 15)) * 80 + (uint32_t)(lane >> 4) * 16;
    const uint32_t boff = sb + 20480 + (uint32_t)(wn * 64 + (lane & 15)) * 80 + (uint32_t)(lane >> 4) * 16;

    const int r = tid >> 1;
    const uint32_t sA = (uint32_t)r * 80 + (uint32_t)(tid & 1) * 32;
    const char* agh = (const char*)(Ah + (size_t)(m0 + r) * K) + (tid & 1) * 32;
    const char* agl = (const char*)(Al + (size_t)(m0 + r) * K) + (tid & 1) * 32;
    const char* bgh = (const char*)(Bh + (size_t)(n0 + r) * K) + (tid & 1) * 32;

#define PREFETCH(st, kt) do { \
    const uint32_t _d = sb + (uint32_t)(st) * STG + sA; \
    const size_t _o = (size_t)(kt) * 64; \
    CP16(_d,          agh + _o); CP16(_d + 16,          agh + _o + 16); \
    CP16(_d + 10240,  agl + _o); CP16(_d + 10240 + 16,  agl + _o + 16); \
    CP16(_d + 20480,  bgh + _o); CP16(_d + 20480 + 16,  bgh + _o + 16); \
    CPCOMMIT(); \
} while (0)

    float acc[2][8][4];
#pragma unroll
    for (int i = 0; i < 2; i++)
#pragma unroll
        for (int j = 0; j < 8; j++)
#pragma unroll
            for (int l = 0; l < 4; l++) acc[i][j][l] = 0.f;

    const int nk = K >> 5;   // >= 64 for all our K
    PREFETCH(0, 0);
    PREFETCH(1, 1);

    int st = 0;
    for (int kt = 0; kt < nk; kt++) {
        if (kt + 2 < nk) CPWAIT1(); else CPWAIT0();
        __syncthreads();
        if (kt + 2 < nk) {
            int ns = st + 2; if (ns >= 3) ns -= 3;
            PREFETCH(ns, kt + 2);
        }
        const uint32_t so = (uint32_t)st * STG;

#pragma unroll
        for (int kk = 0; kk < 2; kk++) {
            uint32_t ah[2][4], al[2][4], bh[4][4];
#pragma unroll
            for (int mt = 0; mt < 2; mt++) {
                ldsm4(ah[mt], aoff + so + mt * 1280 + kk * 32);
                ldsm4(al[mt], aoff + so + 10240 + mt * 1280 + kk * 32);
            }
#pragma unroll
            for (int g = 0; g < 4; g++) ldsm4(bh[g], boff + so + g * 1280 + kk * 32);
#pragma unroll
            for (int mt = 0; mt < 2; mt++)
#pragma unroll
                for (int nt = 0; nt < 8; nt++) {
                    const int g = nt >> 1, o = nt & 1;
                    uint32_t bf[2] = {bh[g][o], bh[g][o + 2]};
                    mma16816(acc[mt][nt], ah[mt], bf);
                    mma16816(acc[mt][nt], al[mt], bf);
                }
        }
        __syncthreads();   // stage st reads done before any warp prefetches into it
        if (++st == 3) st = 0;
    }

    const int rb = m0 + wm * 32 + (lane >> 2);
    const int cb = n0 + wn * 64 + (lane & 3) * 2;
#pragma unroll
    for (int mt = 0; mt < 2; mt++)
#pragma unroll
        for (int nt = 0; nt < 8; nt++) {
            const int r0 = rb + mt * 16;
            const int c = cb + nt * 8;
            float2 v0 = make_float2(alpha * acc[mt][nt][0], alpha * acc[mt][nt][1]);
            float2 v1 = make_float2(alpha * acc[mt][nt][2], alpha * acc[mt][nt][3]);
            if (add) {
                float2 d0 = *(const float2*)(add + (size_t)r0 * ldc + c);
                float2 d1 = *(const float2*)(add + (size_t)(r0 + 8) * ldc + c);
                v0.x += d0.x; v0.y += d0.y; v1.x += d1.x; v1.y += d1.y;
            }
            *(float2*)(C + (size_t)r0 * ldc + c) = v0;
            *(float2*)(C + (size_t)(r0 + 8) * ldc + c) = v1;
        }
}

// =================================================================
// flash attention: fp16. Q split hi/lo (A operands), K,V single fp16
// (B operands). K/V double-buffered cp.async. V via ldmatrix.trans.
// smem: QH 0, QL 34816, KH{0,1} 69632/104448, VH{0,1} 139264/174080,
//       SID{0,1} 208896/209408. rows at 272 B stride.
// =================================================================
#define FQH 0
#define FQL 34816
#define FKH0 69632
#define FKH1 104448
#define FVH0 139264
#define FVH1 174080
#define FSD0 208896
#define FSD1 209408
#define FL_SMEM 209920

__global__ void __launch_bounds__(256, 1) flash_attn(
    const __half* __restrict__ qh, const __half* __restrict__ ql,
    const __half* __restrict__ kh, const __half* __restrict__ vh,
    const int* __restrict__ sid,
    __half* __restrict__ aoh, __half* __restrict__ aol) {
    extern __shared__ char sm[];
    const int z = blockIdx.x;
    const int ib = 15 - (z >> 4);     // descending size (LPT)
    const int h = z & 15;
    const int kvh = h >> 1;
    const int tid = threadIdx.x, lane = tid & 31, w = tid >> 5;
    const uint32_t sb = smem_to_u32(sm);

    const int r = tid >> 1;
    const uint32_t half_off = (uint32_t)(tid & 1) * 128;   // dst byte offset
    const int hcol = (tid & 1) * 64;                       // src half offset
    const uint32_t dstrow = sb + (uint32_t)r * 272 + half_off;

#define KVLOAD(jb, kdst, vdst) do { \
    const __half* _ks = kh + (size_t)((jb) * 128 + r) * 1024 + kvh * 128 + hcol; \
    const __half* _vs = vh + (size_t)((jb) * 128 + r) * 1024 + kvh * 128 + hcol; \
    _Pragma("unroll") \
    for (int x = 0; x < 8; x++) { \
        CP16(dstrow + (kdst) + x * 16, (const char*)_ks + x * 16); \
        CP16(dstrow + (vdst) + x * 16, (const char*)_vs + x * 16); \
    } \
} while (0)

    // prologue: Q (hi+lo) + KV(0) + sid(0), one commit group
    {
        const __half* qsh = qh + (size_t)(ib * 128 + r) * 2048 + h * 128 + hcol;
        const __half* qsl = ql + (size_t)(ib * 128 + r) * 2048 + h * 128 + hcol;
#pragma unroll
        for (int x = 0; x < 8; x++) {
            CP16(dstrow + FQH + x * 16, (const char*)qsh + x * 16);
            CP16(dstrow + FQL + x * 16, (const char*)qsl + x * 16);
        }
        KVLOAD(0, FKH0, FVH0);
        CPCOMMIT();
        if (tid < 128) ((int*)(sm + FSD0))[tid] = sid[tid];   // jb=0 rows 0..127
    }

    const int r0g = ib * 128 + w * 16 + (lane >> 2);
    const int sid0 = sid[r0g], sid1 = sid[r0g + 8];

    float m0 = -1e30f, m1 = -1e30f, l0 = 0.f, l1 = 0.f;
    float oa[16][4];
#pragma unroll
    for (int i = 0; i < 16; i++)
#pragma unroll
        for (int j = 0; j < 4; j++) oa[i][j] = 0.f;

    const uint32_t arh = sb + FQH + (uint32_t)(w * 16 + (lane & 15)) * 272 + (uint32_t)(lane >> 4) * 16;
    const uint32_t arl = arh + (FQL - FQH);
    // V trans-ldsm lane address components
    const int vg = lane >> 3, vlr = lane & 7;
    const uint32_t vrow_off = (uint32_t)((vg & 1) * 8 + vlr) * 272 + (uint32_t)(vg >> 1) * 16;

    for (int jb = 0; jb <= ib; jb++) {
        const int buf = jb & 1;
        const uint32_t kbase = sb + (buf ? FKH1 : FKH0);
        const uint32_t vbase = sb + (buf ? FVH1 : FVH0);
        const int* sid_sm = (const int*)(sm + (buf ? FSD1 : FSD0));

        CPWAIT0();
        __syncthreads();
        if (jb < ib) {
            if (buf) KVLOAD(jb + 1, FKH0, FVH0); else KVLOAD(jb + 1, FKH1, FVH1);
            CPCOMMIT();
            if (tid < 128) ((int*)(sm + (buf ? FSD0 : FSD1)))[tid] = sid[(jb + 1) * 128 + tid];
        }

        // ---- S = Q @ K^T (2-term) ----
        float s[16][4];
#pragma unroll
        for (int i = 0; i < 16; i++)
#pragma unroll
            for (int j = 0; j < 4; j++) s[i][j] = 0.f;

#pragma unroll
        for (int kk = 0; kk < 8; kk++) {
            uint32_t ah[4], al[4];
            ldsm4(ah, arh + kk * 32);
            ldsm4(al, arl + kk * 32);
#pragma unroll
            for (int ng = 0; ng < 8; ng++) {
                uint32_t bh[4];
                ldsm4(bh, kbase + (uint32_t)(ng * 16 + (lane & 15)) * 272
                              + (uint32_t)(lane >> 4) * 16 + kk * 32);
#pragma unroll
                for (int o = 0; o < 2; o++) {
                    uint32_t bf[2] = {bh[o], bh[o + 2]};
                    mma16816(s[ng * 2 + o], ah, bf);
                    mma16816(s[ng * 2 + o], al, bf);
                }
            }
        }

        // ---- scale + mask (same sid && causal) ----
        const int cloc = (lane & 3) * 2;
#pragma unroll
        for (int nt = 0; nt < 16; nt++) {
            const int c0l = nt * 8 + cloc;
            const int sc0 = sid_sm[c0l], sc1 = sid_sm[c0l + 1];
            const int c0gl = jb * 128 + c0l;
            s[nt][0] = (sc0 == sid0 && c0gl <= r0g)         ? s[nt][0] * SCALE : -1e30f;
            s[nt][1] = (sc1 == sid0 && c0gl + 1 <= r0g)     ? s[nt][1] * SCALE : -1e30f;
            s[nt][2] = (sc0 == sid1 && c0gl <= r0g + 8)     ? s[nt][2] * SCALE : -1e30f;
            s[nt][3] = (sc1 == sid1 && c0gl + 1 <= r0g + 8) ? s[nt][3] * SCALE : -1e30f;
        }

        // ---- online softmax ----
        float tm0 = -1e30f, tm1 = -1e30f;
#pragma unroll
        for (int nt = 0; nt < 16; nt++) {
            tm0 = fmaxf(tm0, fmaxf(s[nt][0], s[nt][1]));
            tm1 = fmaxf(tm1, fmaxf(s[nt][2], s[nt][3]));
        }
        tm0 = fmaxf(tm0, __shfl_xor_sync(~0u, tm0, 1));
        tm0 = fmaxf(tm0, __shfl_xor_sync(~0u, tm0, 2));
        tm1 = fmaxf(tm1, __shfl_xor_sync(~0u, tm1, 1));
        tm1 = fmaxf(tm1, __shfl_xor_sync(~0u, tm1, 2));
        const float nm0 = fmaxf(m0, tm0), nm1 = fmaxf(m1, tm1);
        const float cf0 = __expf(m0 - nm0), cf1 = __expf(m1 - nm1);
        m0 = nm0; m1 = nm1;
        float rs0 = 0.f, rs1 = 0.f;
#pragma unroll
        for (int nt = 0; nt < 16; nt++) {
            float p0 = (s[nt][0] > -1e29f) ? __expf(s[nt][0] - nm0) : 0.f;
            float p1 = (s[nt][1] > -1e29f) ? __expf(s[nt][1] - nm0) : 0.f;
            float p2 = (s[nt][2] > -1e29f) ? __expf(s[nt][2] - nm1) : 0.f;
            float p3 = (s[nt][3] > -1e29f) ? __expf(s[nt][3] - nm1) : 0.f;
            s[nt][0] = p0; s[nt][1] = p1; s[nt][2] = p2; s[nt][3] = p3;
            rs0 += p0 + p1; rs1 += p2 + p3;
        }
        l0 = l0 * cf0 + rs0;
        l1 = l1 * cf1 + rs1;
#pragma unroll
        for (int nt = 0; nt < 16; nt++) {
            oa[nt][0] *= cf0; oa[nt][1] *= cf0;
            oa[nt][2] *= cf1; oa[nt][3] *= cf1;
        }

        // ---- O += P @ V (2-term; V via trans-ldsm) ----
#pragma unroll
        for (int kp = 0; kp < 8; kp++) {
            uint32_t pah[4], pal[4];
            {
                const float* t0 = s[kp * 2];
                const float* t1 = s[kp * 2 + 1];
                split2_h(t0[0], t0[1], pah[0], pal[0]);
                split2_h(t0[2], t0[3], pah[1], pal[1]);
                split2_h(t1[0], t1[1], pah[2], pal[2]);
                split2_h(t1[2], t1[3], pah[3], pal[3]);
            }
            const uint32_t vk = vbase + (uint32_t)(kp * 16) * 272 + vrow_off;
#pragma unroll
            for (int ng = 0; ng < 8; ng++) {
                uint32_t vb[4];
                ldsm4t(vb, vk + ng * 32);
#pragma unroll
                for (int o = 0; o < 2; o++) {
                    uint32_t bf[2] = {vb[o * 2], vb[o * 2 + 1]};
                    mma16816(oa[ng * 2 + o], pah, bf);
                    mma16816(oa[ng * 2 + o], pal, bf);
                }
            }
        }
    }

    // ---- epilogue: normalize, split fp16 hi/lo ----
    l0 += __shfl_xor_sync(~0u, l0, 1); l0 += __shfl_xor_sync(~0u, l0, 2);
    l1 += __shfl_xor_sync(~0u, l1, 1); l1 += __shfl_xor_sync(~0u, l1, 2);
    const float i0 = 1.f / l0, i1 = 1.f / l1;
    const int cbase = h * D + (lane & 3) * 2;
    uint32_t* oh0 = (uint32_t*)aoh + (((size_t)r0g * 2048 + cbase) >> 1);
    uint32_t* ol0 = (uint32_t*)aol + (((size_t)r0g * 2048 + cbase) >> 1);
    uint32_t* oh1 = (uint32_t*)aoh + (((size_t)(r0g + 8) * 2048 + cbase) >> 1);
    uint32_t* ol1 = (uint32_t*)aol + (((size_t)(r0g + 8) * 2048 + cbase) >> 1);
#pragma unroll
    for (int nt = 0; nt < 16; nt++) {
        uint32_t hi, lo;
        split2_h(oa[nt][0] * i0, oa[nt][1] * i0, hi, lo);
        oh0[nt * 4] = hi; ol0[nt * 4] = lo;
        split2_h(oa[nt][2] * i1, oa[nt][3] * i1, hi, lo);
        oh1[nt * 4] = hi; ol1[nt * 4] = lo;
    }
}

// ================= elementwise kernels =================
__global__ void split16_kernel(const float* __restrict__ in, __half* __restrict__ oh, int n2) {
    int i = blockIdx.x * blockDim.x + threadIdx.x;
    if (i >= n2) return;
    float2 a = ((const float2*)in)[i];
    ((uint32_t*)oh)[i] = pack_h2(a.x, a.y);
}

__global__ void rmsnorm_split(const float* __restrict__ x, const float* __restrict__ w,
                              __half* __restrict__ oh, __half* __restrict__ ol, int dim) {
    int row = blockIdx.x;
    const float* xr = x + (size_t)row * dim;
    float ss = 0.f;
    for (int i = threadIdx.x; i < dim; i += blockDim.x) { float v = xr[i]; ss += v * v; }
    __shared__ float red[32];
    for (int o = 16; o; o >>= 1) ss += __shfl_xor_sync(~0u, ss, o);
    if ((threadIdx.x & 31) == 0) red[threadIdx.x >> 5] = ss;
    __syncthreads();
    if (threadIdx.x < 32) {
        float v = (threadIdx.x < (blockDim.x >> 5)) ? red[threadIdx.x] : 0.f;
        for (int o = 16; o; o >>= 1) v += __shfl_xor_sync(~0u, v, o);
        if (threadIdx.x == 0) red[0] = v;
    }
    __syncthreads();
    float inv = rsqrtf(red[0] / (float)dim + 1e-6f);
    for (int i = threadIdx.x * 2; i < dim; i += blockDim.x * 2) {
        float v0 = xr[i] * inv * w[i];
        float v1 = xr[i + 1] * inv * w[i + 1];
        uint32_t hi, lo;
        split2_h(v0, v1, hi, lo);
        ((uint32_t*)oh)[((size_t)row * dim + i) >> 1] = hi;
        ((uint32_t*)ol)[((size_t)row * dim + i) >> 1] = lo;
    }
}

// rope + fp16 split of merged qkv: q -> qh/ql (hi+lo), k -> kh (hi, roped), v -> vh (hi)
__global__ void rope_split(const float* __restrict__ qkv, const int* __restrict__ pos,
                           __half* __restrict__ qh, __half* __restrict__ ql,
                           __half* __restrict__ kh, __half* __restrict__ vh) {
    int idx = blockIdx.x * blockDim.x + threadIdx.x;
    if (idx >= SEQ * 32 * 64) return;
    int j = idx & 63;
    int slot = (idx >> 6) & 31;
    int srow = idx >> 11;
    const float* base = qkv + (size_t)srow * 4096 + slot * 128;
    float x0 = base[j], x1 = base[j + 64];
    float y0, y1;
    if (slot < 24) {
        float p = (float)pos[srow];
        float invf = __expf(-(float)j * (logf(10000.f) / 64.f));
        float ang = p * invf;
        float c = cosf(ang), sn = sinf(ang);
        y0 = x0 * c - x1 * sn;
        y1 = x1 * c + x0 * sn;
    } else { y0 = x0; y1 = x1; }
    if (slot < 16) {
        size_t o = (size_t)srow * 2048 + slot * 128;
        __half h0 = __float2half_rn(y0), h1 = __float2half_rn(y1);
        qh[o + j] = h0;      qh[o + j + 64] = h1;
        ql[o + j] = __float2half_rn(y0 - __half2float(h0));
        ql[o + j + 64] = __float2half_rn(y1 - __half2float(h1));
    } else if (slot < 24) {
        size_t o = (size_t)srow * 1024 + (slot - 16) * 128;
        kh[o + j] = __float2half_rn(y0);
        kh[o + j + 64] = __float2half_rn(y1);
    } else {
        size_t o = (size_t)srow * 1024 + (slot - 24) * 128;
        vh[o + j] = __float2half_rn(y0);
        vh[o + j + 64] = __float2half_rn(y1);
    }
}

__global__ void silu_mul_split(const float* __restrict__ gu,
                               __half* __restrict__ oh, __half* __restrict__ ol) {
    size_t i = (size_t)blockIdx.x * blockDim.x + threadIdx.x;
    if (i >= (size_t)SEQ * INTERM / 2) return;
    int row = (int)(i / (INTERM / 2));
    int cp = (int)(i % (INTERM / 2));
    const float* gr = gu + (size_t)row * 16384;
    float g0 = gr[cp * 2], g1 = gr[cp * 2 + 1];
    float u0 = gr[8192 + cp * 2], u1 = gr[8192 + cp * 2 + 1];
    float v0 = g0 / (1.f + __expf(-g0)) * u0;
    float v1 = g1 / (1.f + __expf(-g1)) * u1;
    uint32_t hi, lo;
    split2_h(v0, v1, hi, lo);
    ((uint32_t*)oh)[i] = hi;
    ((uint32_t*)ol)[i] = lo;
}

extern "C" void kernel_launch(void* const* d_in, const int* in_sizes, int n_in,
                              void* d_out, int out_size) {
    const float* hs  = (const float*)d_in[0];
    const int*   sid = (const int*)d_in[1];
    const int*   pos = (const int*)d_in[2];
    const float* ln1 = (const float*)d_in[3];
    const float* wq  = (const float*)d_in[4];
    const float* wk  = (const float*)d_in[5];
    const float* wv  = (const float*)d_in[6];
    const float* wo  = (const float*)d_in[7];
    const float* ln2 = (const float*)d_in[8];
    const float* wg  = (const float*)d_in[9];
    const float* wu  = (const float*)d_in[10];
    const float* wd  = (const float*)d_in[11];
    float* out = (float*)d_out;

    float *qkv, *hb, *gu;
    __half *xnh, *xnl, *qh, *ql, *kh, *vh, *aoh, *aol, *yh, *yl, *gh, *gl;
    __half *wqkvh, *woh, *wguh, *wdh;
    cudaGetSymbolAddress((void**)&qkv, g_qkv);
    cudaGetSymbolAddress((void**)&hb,  g_hb);
    cudaGetSymbolAddress((void**)&gu,  g_gu);
    cudaGetSymbolAddress((void**)&xnh, g_xnh); cudaGetSymbolAddress((void**)&xnl, g_xnl);
    cudaGetSymbolAddress((void**)&qh,  g_qh);  cudaGetSymbolAddress((void**)&ql,  g_ql);
    cudaGetSymbolAddress((void**)&kh,  g_kh);  cudaGetSymbolAddress((void**)&vh,  g_vh);
    cudaGetSymbolAddress((void**)&aoh, g_aoh); cudaGetSymbolAddress((void**)&aol, g_aol);
    cudaGetSymbolAddress((void**)&yh,  g_yh);  cudaGetSymbolAddress((void**)&yl,  g_yl);
    cudaGetSymbolAddress((void**)&gh,  g_gh);  cudaGetSymbolAddress((void**)&gl,  g_gl);
    cudaGetSymbolAddress((void**)&wqkvh, g_wqkvh);
    cudaGetSymbolAddress((void**)&woh,   g_woh);
    cudaGetSymbolAddress((void**)&wguh,  g_wguh);
    cudaGetSymbolAddress((void**)&wdh,   g_wdh);

    cudaFuncSetAttribute(hmma_gemm, cudaFuncAttributeMaxDynamicSharedMemorySize, HM_SMEM);
    cudaFuncSetAttribute(flash_attn, cudaFuncAttributeMaxDynamicSharedMemorySize, FL_SMEM);

    // 0. weights -> fp16 hi
    split16_kernel<<<(2048 * 2048 / 2 + 255) / 256, 256>>>(wq, wqkvh, 2048 * 2048 / 2);
    split16_kernel<<<(1024 * 2048 / 2 + 255) / 256, 256>>>(wk, wqkvh + 2048 * 2048, 1024 * 2048 / 2);
    split16_kernel<<<(1024 * 2048 / 2 + 255) / 256, 256>>>(wv, wqkvh + 3072 * 2048, 1024 * 2048 / 2);
    split16_kernel<<<(2048 * 2048 / 2 + 255) / 256, 256>>>(wo, woh, 2048 * 2048 / 2);
    split16_kernel<<<(8192 * 2048 / 2 + 255) / 256, 256>>>(wg, wguh, 8192 * 2048 / 2);
    split16_kernel<<<(8192 * 2048 / 2 + 255) / 256, 256>>>(wu, wguh + 8192 * 2048, 8192 * 2048 / 2);
    split16_kernel<<<(2048 * 8192 / 2 + 255) / 256, 256>>>(wd, wdh, 2048 * 8192 / 2);

    // 1. pre-attention RMSNorm (fp16 split out)
    rmsnorm_split<<<SEQ, 256>>>(hs, ln1, xnh, xnl, HID);

    // 2. merged QKV projection
    hmma_gemm<<<dim3(32, 16), 256, HM_SMEM>>>(xnh, xnl, wqkvh, qkv, 4096, nullptr, 1.f, HID);

    // 3. RoPE + fp16 split of q/k/v
    rope_split<<<(SEQ * 32 * 64 + 255) / 256, 256>>>(qkv, pos, qh, ql, kh, vh);

    // 4. fused flash attention
    flash_attn<<<256, 256, FL_SMEM>>>(qh, ql, kh, vh, sid, aoh, aol);

    // 5. h = resid + attn_out @ Wo^T
    hmma_gemm<<<dim3(16, 16), 256, HM_SMEM>>>(aoh, aol, woh, hb, HID, hs, 1.f, 2048);

    // 6. post-attention RMSNorm
    rmsnorm_split<<<SEQ, 256>>>(hb, ln2, yh, yl, HID);

    // 7. merged gate|up projection
    hmma_gemm<<<dim3(128, 16), 256, HM_SMEM>>>(yh, yl, wguh, gu, 16384, nullptr, 1.f, HID);

    // 8. silu(gate)*up -> fp16 split
    silu_mul_split<<<(SEQ * INTERM / 2 + 255) / 256, 256>>>(gu, gh, gl);

    // 9. down projection + residual
    hmma_gemm<<<dim3(16, 16), 256, HM_SMEM>>>(gh, gl, wdh, out, HID, hb, 1.f, INTERM);
}

// round 7
// speedup vs baseline: 8.1380x; 1.7004x over previous
#include <cuda_runtime.h>
#include <cuda_fp16.h>
#include <cstdint>
#include <math.h>

#define SEQ 2048
#define H 16
#define KVH 8
#define D 128
#define HID 2048
#define INTERM 8192
#define SCALE 0.08838834764831845f

// ---------------- scratch (device globals) ----------------
__device__ float  g_qkv[SEQ * 4096];            // q|k|v fp32 from GEMM
__device__ __half g_xnh[SEQ * HID];
__device__ __half g_qh[SEQ * 2048], g_ql[SEQ * 2048];
__device__ __half g_kh[SEQ * 1024], g_vh[SEQ * 1024];
__device__ __half g_aoh[SEQ * 2048];
__device__ float  g_hb[SEQ * HID];
__device__ __half g_yh[SEQ * HID];
__device__ __half g_gh[SEQ * INTERM];
// weights fp16
__device__ __half g_wqkvh[4096 * 2048];
__device__ __half g_woh[2048 * 2048];
__device__ __half g_wguh[16384 * 2048];         // gate/up row-interleaved
__device__ __half g_wdh[2048 * 8192];

// ================= helpers =================
__device__ __forceinline__ uint32_t smem_to_u32(const void* p) {
    uint32_t a;
    asm("{ .reg .u64 t; cvta.to.shared.u64 t, %1; cvt.u32.u64 %0, t; }" : "=r"(a) : "l"(p));
    return a;
}
__device__ __forceinline__ uint32_t pack_h2(float a, float b) {
    __half2 h = __floats2half2_rn(a, b);
    return *reinterpret_cast<uint32_t*>(&h);
}
__device__ __forceinline__ void split2_h(float a, float b, uint32_t& hi, uint32_t& lo) {
    __half ha = __float2half_rn(a), hb = __float2half_rn(b);
    hi = ((uint32_t)*(uint16_t*)&hb << 16) | *(uint16_t*)&ha;
    lo = pack_h2(a - __half2float(ha), b - __half2float(hb));
}
__device__ __forceinline__ void ldsm4(uint32_t* r, uint32_t addr) {
    asm volatile("ldmatrix.sync.aligned.m8n8.x4.shared.b16 {%0,%1,%2,%3}, [%4];"
                 : "=r"(r[0]), "=r"(r[1]), "=r"(r[2]), "=r"(r[3]) : "r"(addr));
}
__device__ __forceinline__ void ldsm4t(uint32_t* r, uint32_t addr) {
    asm volatile("ldmatrix.sync.aligned.m8n8.x4.trans.shared.b16 {%0,%1,%2,%3}, [%4];"
                 : "=r"(r[0]), "=r"(r[1]), "=r"(r[2]), "=r"(r[3]) : "r"(addr));
}
__device__ __forceinline__ void mma16816(float* c, const uint32_t* a, const uint32_t* b) {
    asm volatile(
        "mma.sync.aligned.m16n8k16.row.col.f32.f16.f16.f32 "
        "{%0,%1,%2,%3}, {%4,%5,%6,%7}, {%8,%9}, {%0,%1,%2,%3};"
        : "+f"(c[0]), "+f"(c[1]), "+f"(c[2]), "+f"(c[3])
        : "r"(a[0]), "r"(a[1]), "r"(a[2]), "r"(a[3]), "r"(b[0]), "r"(b[1]));
}
#define CP16(dst, src) \
    asm volatile("cp.async.cg.shared.global [%0], [%1], 16;" :: "r"(dst), "l"(src) : "memory")
#define CPCOMMIT() asm volatile("cp.async.commit_group;" ::: "memory")
#define CPWAIT0()  asm volatile("cp.async.wait_group 0;" ::: "memory")
#define CPWAIT1()  asm volatile("cp.async.wait_group 1;" ::: "memory")
#define CPWAIT2()  asm volatile("cp.async.wait_group 2;" ::: "memory")

// =================================================================
// hmma_gemm<SILU>: C = alpha * A[M,K] @ B[N,K]^T (+ add), fp16 single
// term both sides. 4-stage cp.async, 128x128 tile, K chunk 32.
// SILU: adjacent (even,odd) output cols are (gate,up) -> silu(g)*u,
// fp16 out at half width. stage: Ah@0 (10240), Bh@10240 (20480 B).
// =================================================================
#define STG 20480
#define HM_SMEM (4 * STG)

template <bool SILU>
__global__ void __launch_bounds__(256, 2) hmma_gemm(
    const __half* __restrict__ Ah, const __half* __restrict__ Bh,
    float* __restrict__ C, int ldc,
    const float* __restrict__ add, float alpha, int K,
    __half* __restrict__ HC) {
    extern __shared__ char sm[];
    const int tid = threadIdx.x;
    const int lane = tid & 31, wid = tid >> 5;
    const int wm = wid >> 1, wn = wid & 1;
    const int m0 = blockIdx.y * 128, n0 = blockIdx.x * 128;

    const uint32_t sb = smem_to_u32(sm);
    const uint32_t aoff = sb + (uint32_t)(wm * 32 + (lane & 15)) * 80 + (uint32_t)(lane >> 4) * 16;
    const uint32_t boff = sb + 10240 + (uint32_t)(wn * 64 + (lane & 15)) * 80 + (uint32_t)(lane >> 4) * 16;

    const int r = tid >> 1;
    const uint32_t sA = (uint32_t)r * 80 + (uint32_t)(tid & 1) * 32;
    const char* agh = (const char*)(Ah + (size_t)(m0 + r) * K) + (tid & 1) * 32;
    const char* bgh = (const char*)(Bh + (size_t)(n0 + r) * K) + (tid & 1) * 32;

#define PREFETCH(st, kt) do { \
    const uint32_t _d = sb + (uint32_t)(st) * STG + sA; \
    const size_t _o = (size_t)(kt) * 64; \
    CP16(_d,          agh + _o); CP16(_d + 16,          agh + _o + 16); \
    CP16(_d + 10240,  bgh + _o); CP16(_d + 10240 + 16,  bgh + _o + 16); \
    CPCOMMIT(); \
} while (0)

    float acc[2][8][4];
#pragma unroll
    for (int i = 0; i < 2; i++)
#pragma unroll
        for (int j = 0; j < 8; j++)
#pragma unroll
            for (int l = 0; l < 4; l++) acc[i][j][l] = 0.f;

    const int nk = K >> 5;   // >= 64 for all our K
    PREFETCH(0, 0);
    PREFETCH(1, 1);
    PREFETCH(2, 2);

    for (int kt = 0; kt < nk; kt++) {
        const int rem = nk - kt;
        if (rem > 3)      CPWAIT2();
        else if (rem == 3) CPWAIT2();
        else if (rem == 2) CPWAIT1();
        else               CPWAIT0();
        __syncthreads();
        if (kt + 3 < nk) PREFETCH((kt + 3) & 3, kt + 3);
        const uint32_t so = (uint32_t)(kt & 3) * STG;

#pragma unroll
        for (int kk = 0; kk < 2; kk++) {
            uint32_t ah[2][4], bh[4][4];
#pragma unroll
            for (int mt = 0; mt < 2; mt++)
                ldsm4(ah[mt], aoff + so + mt * 1280 + kk * 32);
#pragma unroll
            for (int g = 0; g < 4; g++) ldsm4(bh[g], boff + so + g * 1280 + kk * 32);
#pragma unroll
            for (int mt = 0; mt < 2; mt++)
#pragma unroll
                for (int nt = 0; nt < 8; nt++) {
                    const int g = nt >> 1, o = nt & 1;
                    uint32_t bf[2] = {bh[g][o], bh[g][o + 2]};
                    mma16816(acc[mt][nt], ah[mt], bf);
                }
        }
    }
    __syncthreads();

    const int rb = m0 + wm * 32 + (lane >> 2);
    const int cb = n0 + wn * 64 + (lane & 3) * 2;
    if (SILU) {
        // cols (c, c+1) = (gate, up) pair -> out col c/2 of width N/2
#pragma unroll
        for (int mt = 0; mt < 2; mt++)
#pragma unroll
            for (int nt = 0; nt < 8; nt++) {
                const int r0 = rb + mt * 16;
                const int oc = (cb + nt * 8) >> 1;
                float g0 = acc[mt][nt][0], u0 = acc[mt][nt][1];
                float g1 = acc[mt][nt][2], u1 = acc[mt][nt][3];
                float v0 = g0 / (1.f + __expf(-g0)) * u0;
                float v1 = g1 / (1.f + __expf(-g1)) * u1;
                HC[(size_t)r0 * (ldc >> 1) + oc] = __float2half_rn(v0);
                HC[(size_t)(r0 + 8) * (ldc >> 1) + oc] = __float2half_rn(v1);
            }
    } else {
#pragma unroll
        for (int mt = 0; mt < 2; mt++)
#pragma unroll
            for (int nt = 0; nt < 8; nt++) {
                const int r0 = rb + mt * 16;
                const int c = cb + nt * 8;
                float2 v0 = make_float2(alpha * acc[mt][nt][0], alpha * acc[mt][nt][1]);
                float2 v1 = make_float2(alpha * acc[mt][nt][2], alpha * acc[mt][nt][3]);
                if (add) {
                    float2 d0 = *(const float2*)(add + (size_t)r0 * ldc + c);
                    float2 d1 = *(const float2*)(add + (size_t)(r0 + 8) * ldc + c);
                    v0.x += d0.x; v0.y += d0.y; v1.x += d1.x; v1.y += d1.y;
                }
                *(float2*)(C + (size_t)r0 * ldc + c) = v0;
                *(float2*)(C + (size_t)(r0 + 8) * ldc + c) = v1;
            }
    }
}

// =================================================================
// flash attention: Q split hi/lo fp16, K,V single fp16.
// K/V double-buffered cp.async. V via ldmatrix.trans. fp16 out (hi).
// =================================================================
#define FQH 0
#define FQL 34816
#define FKH0 69632
#define FKH1 104448
#define FVH0 139264
#define FVH1 174080
#define FSD0 208896
#define FSD1 209408
#define FL_SMEM 209920

__global__ void __launch_bounds__(256, 1) flash_attn(
    const __half* __restrict__ qh, const __half* __restrict__ ql,
    const __half* __restrict__ kh, const __half* __restrict__ vh,
    const int* __restrict__ sid, __half* __restrict__ aoh) {
    extern __shared__ char sm[];
    const int z = blockIdx.x;
    const int ib = 15 - (z >> 4);
    const int h = z & 15;
    const int kvh = h >> 1;
    const int tid = threadIdx.x, lane = tid & 31, w = tid >> 5;
    const uint32_t sb = smem_to_u32(sm);

    const int r = tid >> 1;
    const uint32_t half_off = (uint32_t)(tid & 1) * 128;
    const int hcol = (tid & 1) * 64;
    const uint32_t dstrow = sb + (uint32_t)r * 272 + half_off;

#define KVLOAD(jb, kdst, vdst) do { \
    const __half* _ks = kh + (size_t)((jb) * 128 + r) * 1024 + kvh * 128 + hcol; \
    const __half* _vs = vh + (size_t)((jb) * 128 + r) * 1024 + kvh * 128 + hcol; \
    _Pragma("unroll") \
    for (int x = 0; x < 8; x++) { \
        CP16(dstrow + (kdst) + x * 16, (const char*)_ks + x * 16); \
        CP16(dstrow + (vdst) + x * 16, (const char*)_vs + x * 16); \
    } \
} while (0)

    {
        const __half* qsh = qh + (size_t)(ib * 128 + r) * 2048 + h * 128 + hcol;
        const __half* qsl = ql + (size_t)(ib * 128 + r) * 2048 + h * 128 + hcol;
#pragma unroll
        for (int x = 0; x < 8; x++) {
            CP16(dstrow + FQH + x * 16, (const char*)qsh + x * 16);
            CP16(dstrow + FQL + x * 16, (const char*)qsl + x * 16);
        }
        KVLOAD(0, FKH0, FVH0);
        CPCOMMIT();
        if (tid < 128) ((int*)(sm + FSD0))[tid] = sid[tid];
    }

    const int r0g = ib * 128 + w * 16 + (lane >> 2);
    const int sid0 = sid[r0g], sid1 = sid[r0g + 8];

    float m0 = -1e30f, m1 = -1e30f, l0 = 0.f, l1 = 0.f;
    float oa[16][4];
#pragma unroll
    for (int i = 0; i < 16; i++)
#pragma unroll
        for (int j = 0; j < 4; j++) oa[i][j] = 0.f;

    const uint32_t arh = sb + FQH + (uint32_t)(w * 16 + (lane & 15)) * 272 + (uint32_t)(lane >> 4) * 16;
    const uint32_t arl = arh + (FQL - FQH);
    const int vg = lane >> 3, vlr = lane & 7;
    const uint32_t vrow_off = (uint32_t)((vg & 1) * 8 + vlr) * 272 + (uint32_t)(vg >> 1) * 16;

    for (int jb = 0; jb <= ib; jb++) {
        const int buf = jb & 1;
        const uint32_t kbase = sb + (buf ? FKH1 : FKH0);
        const uint32_t vbase = sb + (buf ? FVH1 : FVH0);
        const int* sid_sm = (const int*)(sm + (buf ? FSD1 : FSD0));

        CPWAIT0();
        __syncthreads();
        if (jb < ib) {
            if (buf) KVLOAD(jb + 1, FKH0, FVH0); else KVLOAD(jb + 1, FKH1, FVH1);
            CPCOMMIT();
            if (tid < 128) ((int*)(sm + (buf ? FSD0 : FSD1)))[tid] = sid[(jb + 1) * 128 + tid];
        }

        float s[16][4];
#pragma unroll
        for (int i = 0; i < 16; i++)
#pragma unroll
            for (int j = 0; j < 4; j++) s[i][j] = 0.f;

#pragma unroll
        for (int kk = 0; kk < 8; kk++) {
            uint32_t ah[4], al[4];
            ldsm4(ah, arh + kk * 32);
            ldsm4(al, arl + kk * 32);
#pragma unroll
            for (int ng = 0; ng < 8; ng++) {
                uint32_t bh[4];
                ldsm4(bh, kbase + (uint32_t)(ng * 16 + (lane & 15)) * 272
                              + (uint32_t)(lane >> 4) * 16 + kk * 32);
#pragma unroll
                for (int o = 0; o < 2; o++) {
                    uint32_t bf[2] = {bh[o], bh[o + 2]};
                    mma16816(s[ng * 2 + o], ah, bf);
                    mma16816(s[ng * 2 + o], al, bf);
                }
            }
        }

        const int cloc = (lane & 3) * 2;
#pragma unroll
        for (int nt = 0; nt < 16; nt++) {
            const int c0l = nt * 8 + cloc;
            const int sc0 = sid_sm[c0l], sc1 = sid_sm[c0l + 1];
            const int c0gl = jb * 128 + c0l;
            s[nt][0] = (sc0 == sid0 && c0gl <= r0g)         ? s[nt][0] * SCALE : -1e30f;
            s[nt][1] = (sc1 == sid0 && c0gl + 1 <= r0g)     ? s[nt][1] * SCALE : -1e30f;
            s[nt][2] = (sc0 == sid1 && c0gl <= r0g + 8)     ? s[nt][2] * SCALE : -1e30f;
            s[nt][3] = (sc1 == sid1 && c0gl + 1 <= r0g + 8) ? s[nt][3] * SCALE : -1e30f;
        }

        float tm0 = -1e30f, tm1 = -1e30f;
#pragma unroll
        for (int nt = 0; nt < 16; nt++) {
            tm0 = fmaxf(tm0, fmaxf(s[nt][0], s[nt][1]));
            tm1 = fmaxf(tm1, fmaxf(s[nt][2], s[nt][3]));
        }
        tm0 = fmaxf(tm0, __shfl_xor_sync(~0u, tm0, 1));
        tm0 = fmaxf(tm0, __shfl_xor_sync(~0u, tm0, 2));
        tm1 = fmaxf(tm1, __shfl_xor_sync(~0u, tm1, 1));
        tm1 = fmaxf(tm1, __shfl_xor_sync(~0u, tm1, 2));
        const float nm0 = fmaxf(m0, tm0), nm1 = fmaxf(m1, tm1);
        const float cf0 = __expf(m0 - nm0), cf1 = __expf(m1 - nm1);
        m0 = nm0; m1 = nm1;
        float rs0 = 0.f, rs1 = 0.f;
#pragma unroll
        for (int nt = 0; nt < 16; nt++) {
            float p0 = (s[nt][0] > -1e29f) ? __expf(s[nt][0] - nm0) : 0.f;
            float p1 = (s[nt][1] > -1e29f) ? __expf(s[nt][1] - nm0) : 0.f;
            float p2 = (s[nt][2] > -1e29f) ? __expf(s[nt][2] - nm1) : 0.f;
            float p3 = (s[nt][3] > -1e29f) ? __expf(s[nt][3] - nm1) : 0.f;
            s[nt][0] = p0; s[nt][1] = p1; s[nt][2] = p2; s[nt][3] = p3;
            rs0 += p0 + p1; rs1 += p2 + p3;
        }
        l0 = l0 * cf0 + rs0;
        l1 = l1 * cf1 + rs1;
#pragma unroll
        for (int nt = 0; nt < 16; nt++) {
            oa[nt][0] *= cf0; oa[nt][1] *= cf0;
            oa[nt][2] *= cf1; oa[nt][3] *= cf1;
        }

#pragma unroll
        for (int kp = 0; kp < 8; kp++) {
            uint32_t pah[4], pal[4];
            {
                const float* t0 = s[kp * 2];
                const float* t1 = s[kp * 2 + 1];
                split2_h(t0[0], t0[1], pah[0], pal[0]);
                split2_h(t0[2], t0[3], pah[1], pal[1]);
                split2_h(t1[0], t1[1], pah[2], pal[2]);
                split2_h(t1[2], t1[3], pah[3], pal[3]);
            }
            const uint32_t vk = vbase + (uint32_t)(kp * 16) * 272 + vrow_off;
#pragma unroll
            for (int ng = 0; ng < 8; ng++) {
                uint32_t vb[4];
                ldsm4t(vb, vk + ng * 32);
#pragma unroll
                for (int o = 0; o < 2; o++) {
                    uint32_t bf[2] = {vb[o * 2], vb[o * 2 + 1]};
                    mma16816(oa[ng * 2 + o], pah, bf);
                    mma16816(oa[ng * 2 + o], pal, bf);
                }
            }
        }
    }

    l0 += __shfl_xor_sync(~0u, l0, 1); l0 += __shfl_xor_sync(~0u, l0, 2);
    l1 += __shfl_xor_sync(~0u, l1, 1); l1 += __shfl_xor_sync(~0u, l1, 2);
    const float i0 = 1.f / l0, i1 = 1.f / l1;
    const int cbase = h * D + (lane & 3) * 2;
    uint32_t* oh0 = (uint32_t*)aoh + (((size_t)r0g * 2048 + cbase) >> 1);
    uint32_t* oh1 = (uint32_t*)aoh + (((size_t)(r0g + 8) * 2048 + cbase) >> 1);
#pragma unroll
    for (int nt = 0; nt < 16; nt++) {
        oh0[nt * 4] = pack_h2(oa[nt][0] * i0, oa[nt][1] * i0);
        oh1[nt * 4] = pack_h2(oa[nt][2] * i1, oa[nt][3] * i1);
    }
}

// ================= elementwise kernels =================
__global__ void split16_kernel(const float* __restrict__ in, __half* __restrict__ oh, int n2) {
    int i = blockIdx.x * blockDim.x + threadIdx.x;
    if (i >= n2) return;
    float2 a = ((const float2*)in)[i];
    ((uint32_t*)oh)[i] = pack_h2(a.x, a.y);
}

// interleave wg/wu rows: dst row 2j = wg[j], 2j+1 = wu[j]
__global__ void interleave16_kernel(const float* __restrict__ wg, const float* __restrict__ wu,
                                    __half* __restrict__ dst) {
    int i = blockIdx.x * blockDim.x + threadIdx.x;   // pair index over 8192*1024
    if (i >= INTERM * (HID / 2)) return;
    int j = i / (HID / 2), cp = i % (HID / 2);
    float2 a = ((const float2*)wg)[i];
    float2 b = ((const float2*)wu)[i];
    ((uint32_t*)dst)[(size_t)(2 * j) * (HID / 2) + cp] = pack_h2(a.x, a.y);
    ((uint32_t*)dst)[(size_t)(2 * j + 1) * (HID / 2) + cp] = pack_h2(b.x, b.y);
}

__global__ void rmsnorm16(const float* __restrict__ x, const float* __restrict__ w,
                          __half* __restrict__ oh, int dim) {
    int row = blockIdx.x;
    const float* xr = x + (size_t)row * dim;
    float ss = 0.f;
    for (int i = threadIdx.x; i < dim; i += blockDim.x) { float v = xr[i]; ss += v * v; }
    __shared__ float red[32];
    for (int o = 16; o; o >>= 1) ss += __shfl_xor_sync(~0u, ss, o);
    if ((threadIdx.x & 31) == 0) red[threadIdx.x >> 5] = ss;
    __syncthreads();
    if (threadIdx.x < 32) {
        float v = (threadIdx.x < (blockDim.x >> 5)) ? red[threadIdx.x] : 0.f;
        for (int o = 16; o; o >>= 1) v += __shfl_xor_sync(~0u, v, o);
        if (threadIdx.x == 0) red[0] = v;
    }
    __syncthreads();
    float inv = rsqrtf(red[0] / (float)dim + 1e-6f);
    for (int i = threadIdx.x * 2; i < dim; i += blockDim.x * 2) {
        float v0 = xr[i] * inv * w[i];
        float v1 = xr[i + 1] * inv * w[i + 1];
        ((uint32_t*)oh)[((size_t)row * dim + i) >> 1] = pack_h2(v0, v1);
    }
}

__global__ void rope_split(const float* __restrict__ qkv, const int* __restrict__ pos,
                           __half* __restrict__ qh, __half* __restrict__ ql,
                           __half* __restrict__ kh, __half* __restrict__ vh) {
    int idx = blockIdx.x * blockDim.x + threadIdx.x;
    if (idx >= SEQ * 32 * 64) return;
    int j = idx & 63;
    int slot = (idx >> 6) & 31;
    int srow = idx >> 11;
    const float* base = qkv + (size_t)srow * 4096 + slot * 128;
    float x0 = base[j], x1 = base[j + 64];
    float y0, y1;
    if (slot < 24) {
        float p = (float)pos[srow];
        float invf = __expf(-(float)j * (logf(10000.f) / 64.f));
        float ang = p * invf;
        float c = cosf(ang), sn = sinf(ang);
        y0 = x0 * c - x1 * sn;
        y1 = x1 * c + x0 * sn;
    } else { y0 = x0; y1 = x1; }
    if (slot < 16) {
        size_t o = (size_t)srow * 2048 + slot * 128;
        __half h0 = __float2half_rn(y0), h1 = __float2half_rn(y1);
        qh[o + j] = h0;      qh[o + j + 64] = h1;
        ql[o + j] = __float2half_rn(y0 - __half2float(h0));
        ql[o + j + 64] = __float2half_rn(y1 - __half2float(h1));
    } else if (slot < 24) {
        size_t o = (size_t)srow * 1024 + (slot - 16) * 128;
        kh[o + j] = __float2half_rn(y0);
        kh[o + j + 64] = __float2half_rn(y1);
    } else {
        size_t o = (size_t)srow * 1024 + (slot - 24) * 128;
        vh[o + j] = __float2half_rn(y0);
        vh[o + j + 64] = __float2half_rn(y1);
    }
}

extern "C" void kernel_launch(void* const* d_in, const int* in_sizes, int n_in,
                              void* d_out, int out_size) {
    const float* hs  = (const float*)d_in[0];
    const int*   sid = (const int*)d_in[1];
    const int*   pos = (const int*)d_in[2];
    const float* ln1 = (const float*)d_in[3];
    const float* wq  = (const float*)d_in[4];
    const float* wk  = (const float*)d_in[5];
    const float* wv  = (const float*)d_in[6];
    const float* wo  = (const float*)d_in[7];
    const float* ln2 = (const float*)d_in[8];
    const float* wg  = (const float*)d_in[9];
    const float* wu  = (const float*)d_in[10];
    const float* wd  = (const float*)d_in[11];
    float* out = (float*)d_out;

    float *qkv, *hb;
    __half *xnh, *qh, *ql, *kh, *vh, *aoh, *yh, *gh;
    __half *wqkvh, *woh, *wguh, *wdh;
    cudaGetSymbolAddress((void**)&qkv, g_qkv);
    cudaGetSymbolAddress((void**)&hb,  g_hb);
    cudaGetSymbolAddress((void**)&xnh, g_xnh);
    cudaGetSymbolAddress((void**)&qh,  g_qh);  cudaGetSymbolAddress((void**)&ql, g_ql);
    cudaGetSymbolAddress((void**)&kh,  g_kh);  cudaGetSymbolAddress((void**)&vh, g_vh);
    cudaGetSymbolAddress((void**)&aoh, g_aoh);
    cudaGetSymbolAddress((void**)&yh,  g_yh);
    cudaGetSymbolAddress((void**)&gh,  g_gh);
    cudaGetSymbolAddress((void**)&wqkvh, g_wqkvh);
    cudaGetSymbolAddress((void**)&woh,   g_woh);
    cudaGetSymbolAddress((void**)&wguh,  g_wguh);
    cudaGetSymbolAddress((void**)&wdh,   g_wdh);

    cudaFuncSetAttribute(hmma_gemm<false>, cudaFuncAttributeMaxDynamicSharedMemorySize, HM_SMEM);
    cudaFuncSetAttribute(hmma_gemm<true>,  cudaFuncAttributeMaxDynamicSharedMemorySize, HM_SMEM);
    cudaFuncSetAttribute(flash_attn, cudaFuncAttributeMaxDynamicSharedMemorySize, FL_SMEM);

    // 0. weights -> fp16 (gate/up row-interleaved)
    split16_kernel<<<(2048 * 2048 / 2 + 255) / 256, 256>>>(wq, wqkvh, 2048 * 2048 / 2);
    split16_kernel<<<(1024 * 2048 / 2 + 255) / 256, 256>>>(wk, wqkvh + 2048 * 2048, 1024 * 2048 / 2);
    split16_kernel<<<(1024 * 2048 / 2 + 255) / 256, 256>>>(wv, wqkvh + 3072 * 2048, 1024 * 2048 / 2);
    split16_kernel<<<(2048 * 2048 / 2 + 255) / 256, 256>>>(wo, woh, 2048 * 2048 / 2);
    interleave16_kernel<<<(INTERM * (HID / 2) + 255) / 256, 256>>>(wg, wu, wguh);
    split16_kernel<<<(2048 * 8192 / 2 + 255) / 256, 256>>>(wd, wdh, 2048 * 8192 / 2);

    // 1. pre-attention RMSNorm -> fp16
    rmsnorm16<<<SEQ, 256>>>(hs, ln1, xnh, HID);

    // 2. merged QKV projection (fp32 out for rope)
    hmma_gemm<false><<<dim3(32, 16), 256, HM_SMEM>>>(xnh, wqkvh, qkv, 4096, nullptr, 1.f, HID, nullptr);

    // 3. RoPE + fp16 split of q (hi/lo) / k / v
    rope_split<<<(SEQ * 32 * 64 + 255) / 256, 256>>>(qkv, pos, qh, ql, kh, vh);

    // 4. fused flash attention -> fp16
    flash_attn<<<256, 256, FL_SMEM>>>(qh, ql, kh, vh, sid, aoh);

    // 5. h = resid + attn_out @ Wo^T
    hmma_gemm<false><<<dim3(16, 16), 256, HM_SMEM>>>(aoh, woh, hb, HID, hs, 1.f, 2048, nullptr);

    // 6. post-attention RMSNorm -> fp16
    rmsnorm16<<<SEQ, 256>>>(hb, ln2, yh, HID);

    // 7. gate|up interleaved projection with fused SiLU -> fp16 gh[2048][8192]
    hmma_gemm<true><<<dim3(128, 16), 256, HM_SMEM>>>(yh, wguh, nullptr, 16384, nullptr, 1.f, HID, gh);

    // 8. down projection + residual -> out
    hmma_gemm<false><<<dim3(16, 16), 256, HM_SMEM>>>(gh, wdh, out, HID, hb, 1.f, INTERM, nullptr);
}